// round 1
// baseline (speedup 1.0000x reference)
#include <cuda_runtime.h>
#include <math.h>
#include <stdint.h>

// Problem dims (fixed for this instance)
#define BB   4
#define LL   2048
#define DM   768
#define DIN  1536
#define NN   16
#define KK   4
#define BL   (BB*LL)          // 8192 tokens

// ----------------------------------------------------------------------------
// Device scratch (static allocations — no cudaMalloc allowed)
// ----------------------------------------------------------------------------
__device__ float g_xn1[BL*DM];          // rmsnorm(x, norm_w)
__device__ float g_xn2[BL*DM];          // rmsnorm(xn1, in_norm_w)
__device__ float g_xz [BL*2*DIN];       // bitlinear output [x_path | z]
__device__ float g_xc [BL*DIN];         // conv + silu
__device__ float g_dbc[BL*33];          // [dt | B(16) | C(16)]
__device__ float g_y  [BL*DIN];         // scan output * silu(z)
__device__ float g_yn [BL*DIN];         // rmsnorm(y, out_norm_w)
__device__ float g_WqIn [2*DIN*DM];     // quantized (scale-folded) W_in
__device__ float g_WqOut[DM*DIN];       // quantized (scale-folded) W_out
__device__ float g_part[512];           // reduction partials (256 each)
__device__ float g_scale[2];            // scales for W_in / W_out

// ----------------------------------------------------------------------------
// Helpers
// ----------------------------------------------------------------------------
__device__ __forceinline__ float block_reduce_sum(float v, float* sred) {
    #pragma unroll
    for (int s = 16; s; s >>= 1) v += __shfl_xor_sync(0xffffffffu, v, s);
    int w = threadIdx.x >> 5;
    __syncthreads();
    if ((threadIdx.x & 31) == 0) sred[w] = v;
    __syncthreads();
    float t = 0.f;
    int nw = blockDim.x >> 5;
    for (int i = 0; i < nw; i++) t += sred[i];
    return t;
}

__device__ __forceinline__ float silu_f(float x) {
    return x / (1.f + __expf(-x));
}

// ----------------------------------------------------------------------------
// Weight quantization (deterministic 2-phase mean|W|)
// ----------------------------------------------------------------------------
__global__ void abssum_kernel(const float* __restrict__ W, int n, float* __restrict__ part) {
    __shared__ float sred[8];
    float s = 0.f;
    for (int i = blockIdx.x * blockDim.x + threadIdx.x; i < n; i += gridDim.x * blockDim.x)
        s += fabsf(W[i]);
    float tot = block_reduce_sum(s, sred);
    if (threadIdx.x == 0) part[blockIdx.x] = tot;
}

__global__ void finalize_scale_kernel(const float* __restrict__ part, float* __restrict__ scale, float inv_n) {
    __shared__ float sred[8];
    float tot = block_reduce_sum(part[threadIdx.x], sred);
    if (threadIdx.x == 0) *scale = fmaxf(tot * inv_n, 1e-5f);
}

__global__ void quant_kernel(const float* __restrict__ W, float* __restrict__ Wq, int n,
                             const float* __restrict__ sp) {
    float scale = *sp;
    for (int i = blockIdx.x * blockDim.x + threadIdx.x; i < n; i += gridDim.x * blockDim.x) {
        float wn = W[i] / scale;
        wn = fminf(fmaxf(wn, -1.f), 1.f);
        Wq[i] = rintf(wn) * scale;   // rintf = round-half-even, matches jnp.round
    }
}

// ----------------------------------------------------------------------------
// RMSNorm (one block per row)
// ----------------------------------------------------------------------------
template <int CNT>
__global__ void rmsnorm_kernel(const float* __restrict__ in, const float* __restrict__ w,
                               float* __restrict__ out) {
    __shared__ float sred[8];
    const int D = CNT * 256;
    size_t base = (size_t)blockIdx.x * D;
    float v[CNT];
    float ss = 0.f;
    #pragma unroll
    for (int i = 0; i < CNT; i++) {
        float x = in[base + threadIdx.x + (i << 8)];
        v[i] = x;
        ss = fmaf(x, x, ss);
    }
    float tot = block_reduce_sum(ss, sred);
    float r = rsqrtf(tot / (float)D + 1e-6f);
    #pragma unroll
    for (int i = 0; i < CNT; i++) {
        int c = threadIdx.x + (i << 8);
        out[base + c] = v[i] * r * w[c];
    }
}

// ----------------------------------------------------------------------------
// SGEMM: C[M,N] = A[M,K] * B[N,K]^T (+ residual). 128x128x16, 8x8/thread.
// M,N multiples of 128; K multiple of 16 and of 4 (float4 loads).
// ----------------------------------------------------------------------------
__global__ __launch_bounds__(256)
void sgemm_kernel(const float* __restrict__ A, const float* __restrict__ B,
                  float* __restrict__ C, const float* __restrict__ Res,
                  int M, int N, int K) {
    const int BK = 16;
    __shared__ float As[BK][128];
    __shared__ float Bs[BK][128];

    int bm = blockIdx.y * 128;
    int bn = blockIdx.x * 128;
    int tid = threadIdx.x;
    int tx = tid & 15;          // N direction (x8)
    int ty = tid >> 4;          // M direction (x8)

    float acc[8][8];
    #pragma unroll
    for (int i = 0; i < 8; i++)
        #pragma unroll
        for (int j = 0; j < 8; j++) acc[i][j] = 0.f;

    for (int k0 = 0; k0 < K; k0 += BK) {
        #pragma unroll
        for (int it = 0; it < 2; ++it) {
            int idx = tid + it * 256;       // 0..511  (128 rows x 4 float4)
            int r  = idx >> 2;
            int kq = (idx & 3) << 2;
            float4 a = *(const float4*)(A + (size_t)(bm + r) * K + k0 + kq);
            As[kq + 0][r] = a.x; As[kq + 1][r] = a.y; As[kq + 2][r] = a.z; As[kq + 3][r] = a.w;
            float4 b = *(const float4*)(B + (size_t)(bn + r) * K + k0 + kq);
            Bs[kq + 0][r] = b.x; Bs[kq + 1][r] = b.y; Bs[kq + 2][r] = b.z; Bs[kq + 3][r] = b.w;
        }
        __syncthreads();
        #pragma unroll
        for (int k = 0; k < BK; k++) {
            float ra[8], rb[8];
            float4 a0 = *(const float4*)&As[k][ty * 8];
            float4 a1 = *(const float4*)&As[k][ty * 8 + 4];
            ra[0]=a0.x; ra[1]=a0.y; ra[2]=a0.z; ra[3]=a0.w;
            ra[4]=a1.x; ra[5]=a1.y; ra[6]=a1.z; ra[7]=a1.w;
            float4 b0 = *(const float4*)&Bs[k][tx * 8];
            float4 b1 = *(const float4*)&Bs[k][tx * 8 + 4];
            rb[0]=b0.x; rb[1]=b0.y; rb[2]=b0.z; rb[3]=b0.w;
            rb[4]=b1.x; rb[5]=b1.y; rb[6]=b1.z; rb[7]=b1.w;
            #pragma unroll
            for (int i = 0; i < 8; i++)
                #pragma unroll
                for (int j = 0; j < 8; j++)
                    acc[i][j] = fmaf(ra[i], rb[j], acc[i][j]);
        }
        __syncthreads();
    }

    #pragma unroll
    for (int i = 0; i < 8; i++) {
        size_t row = bm + ty * 8 + i;
        #pragma unroll
        for (int j4 = 0; j4 < 2; j4++) {
            size_t off = row * N + bn + tx * 8 + j4 * 4;
            float4 o;
            o.x = acc[i][j4 * 4 + 0];
            o.y = acc[i][j4 * 4 + 1];
            o.z = acc[i][j4 * 4 + 2];
            o.w = acc[i][j4 * 4 + 3];
            if (Res) {
                float4 r = *(const float4*)(Res + off);
                o.x += r.x; o.y += r.y; o.z += r.z; o.w += r.w;
            }
            *(float4*)(C + off) = o;
        }
    }
}

// ----------------------------------------------------------------------------
// Causal depthwise conv (K=4) + bias + SiLU, reading x_path slice from g_xz
// ----------------------------------------------------------------------------
__global__ void conv_silu_kernel(const float* __restrict__ cw, const float* __restrict__ cb) {
    int idx = blockIdx.x * blockDim.x + threadIdx.x;
    if (idx >= BL * DIN) return;
    int d = idx % DIN;
    int m = idx / DIN;       // b*L + l
    int l = m & (LL - 1);
    float acc = cb[d];
    #pragma unroll
    for (int k = 0; k < KK; k++) {
        int ll = l + k - (KK - 1);
        if (ll >= 0)
            acc = fmaf(g_xz[(size_t)(m + k - (KK - 1)) * (2 * DIN) + d], cw[d * KK + k], acc);
    }
    g_xc[(size_t)m * DIN + d] = silu_f(acc);
}

// ----------------------------------------------------------------------------
// dbc = xc @ W_x^T   (N_out = 33) — one block per token, one warp per output set
// ----------------------------------------------------------------------------
__global__ void dbc_kernel(const float* __restrict__ Wx) {
    int m = blockIdx.x;
    int warp = threadIdx.x >> 5, lane = threadIdx.x & 31;
    const float4* row = (const float4*)(g_xc + (size_t)m * DIN);
    for (int o = warp; o < 33; o += 8) {
        const float4* w = (const float4*)(Wx + (size_t)o * DIN);
        float acc = 0.f;
        for (int q = lane; q < DIN / 4; q += 32) {
            float4 xv = row[q], wv = w[q];
            acc = fmaf(xv.x, wv.x, fmaf(xv.y, wv.y, fmaf(xv.z, wv.z, fmaf(xv.w, wv.w, acc))));
        }
        #pragma unroll
        for (int s = 16; s; s >>= 1) acc += __shfl_xor_sync(0xffffffffu, acc, s);
        if (!lane) g_dbc[m * 33 + o] = acc;
    }
}

// ----------------------------------------------------------------------------
// Selective scan. Thread = (d-channel, n-group of 4). Lanes 4t..4t+3 share d.
// Also fuses + u*D and * silu(z). Output -> g_y.
// ----------------------------------------------------------------------------
__global__ void scan_kernel(const float* __restrict__ dt_w, const float* __restrict__ dt_b,
                            const float* __restrict__ A_log, const float* __restrict__ D_param) {
    const int DPB = 32;                          // d-channels per block (128 threads)
    int b    = blockIdx.x / (DIN / DPB);
    int dblk = blockIdx.x % (DIN / DPB);
    int ng   = threadIdx.x & 3;
    int dloc = threadIdx.x >> 2;
    int d = dblk * DPB + dloc;

    float A4[4], h[4];
    #pragma unroll
    for (int j = 0; j < 4; j++) {
        A4[j] = -expf(A_log[d * NN + ng * 4 + j]);
        h[j] = 0.f;
    }
    float dtw = dt_w[d], dtb = dt_b[d], Dp = D_param[d];
    size_t mbase = (size_t)b * LL;

    for (int l = 0; l < LL; l++) {
        size_t m = mbase + l;
        const float* dbc = g_dbc + m * 33;
        float dt = __ldg(dbc);
        float sp_in = fmaf(dt, dtw, dtb);
        float delta = (sp_in > 20.f) ? sp_in : log1pf(__expf(sp_in));
        float u  = g_xc[m * DIN + d];
        float du = delta * u;
        float y = 0.f;
        #pragma unroll
        for (int j = 0; j < 4; j++) {
            int n = ng * 4 + j;
            float dA = __expf(delta * A4[j]);
            h[j] = fmaf(dA, h[j], du * __ldg(dbc + 1 + n));
            y = fmaf(h[j], __ldg(dbc + 17 + n), y);
        }
        y += __shfl_xor_sync(0xffffffffu, y, 1);
        y += __shfl_xor_sync(0xffffffffu, y, 2);
        if (ng == 0) {
            float yy = fmaf(u, Dp, y);
            float z = g_xz[m * (2 * DIN) + DIN + d];
            g_y[m * DIN + d] = yy * silu_f(z);
        }
    }
}

// ----------------------------------------------------------------------------
// Launch
// ----------------------------------------------------------------------------
extern "C" void kernel_launch(void* const* d_in, const int* in_sizes, int n_in,
                              void* d_out, int out_size) {
    const float* x        = (const float*)d_in[0];
    const float* norm_w   = (const float*)d_in[1];
    const float* in_norm_w= (const float*)d_in[2];
    const float* W_in     = (const float*)d_in[3];
    const float* conv_w   = (const float*)d_in[4];
    const float* conv_b   = (const float*)d_in[5];
    const float* W_x      = (const float*)d_in[6];
    const float* dt_w     = (const float*)d_in[7];
    const float* dt_b     = (const float*)d_in[8];
    const float* A_log    = (const float*)d_in[9];
    const float* D_param  = (const float*)d_in[10];
    // d_in[11] = out_norm_w, d_in[12] = W_out
    const float* out_norm_w = (const float*)d_in[11];
    const float* W_out      = (const float*)d_in[12];
    float* out = (float*)d_out;

    // Resolve device-global scratch addresses (query only; capture-safe)
    float *p_xn1, *p_xn2, *p_xz, *p_yn, *p_part, *p_scale, *p_WqIn, *p_WqOut, *p_y;
    cudaGetSymbolAddress((void**)&p_xn1,   g_xn1);
    cudaGetSymbolAddress((void**)&p_xn2,   g_xn2);
    cudaGetSymbolAddress((void**)&p_xz,    g_xz);
    cudaGetSymbolAddress((void**)&p_yn,    g_yn);
    cudaGetSymbolAddress((void**)&p_y,     g_y);
    cudaGetSymbolAddress((void**)&p_part,  g_part);
    cudaGetSymbolAddress((void**)&p_scale, g_scale);
    cudaGetSymbolAddress((void**)&p_WqIn,  g_WqIn);
    cudaGetSymbolAddress((void**)&p_WqOut, g_WqOut);

    const int nWin  = 2 * DIN * DM;   // 2359296
    const int nWout = DM * DIN;       // 1179648

    // 1) Weight scales (deterministic two-phase)
    abssum_kernel<<<256, 256>>>(W_in,  nWin,  p_part);
    abssum_kernel<<<256, 256>>>(W_out, nWout, p_part + 256);
    finalize_scale_kernel<<<1, 256>>>(p_part,       p_scale,     1.f / (float)nWin);
    finalize_scale_kernel<<<1, 256>>>(p_part + 256, p_scale + 1, 1.f / (float)nWout);

    // 2) Quantize weights (scale folded in)
    quant_kernel<<<2048, 256>>>(W_in,  p_WqIn,  nWin,  p_scale);
    quant_kernel<<<2048, 256>>>(W_out, p_WqOut, nWout, p_scale + 1);

    // 3) Double RMSNorm on x
    rmsnorm_kernel<3><<<BL, 256>>>(x,     norm_w,    p_xn1);
    rmsnorm_kernel<3><<<BL, 256>>>(p_xn1, in_norm_w, p_xn2);

    // 4) xz = xn2 @ WqIn^T   [8192 x 3072]
    {
        dim3 grid(2 * DIN / 128, BL / 128);
        sgemm_kernel<<<grid, 256>>>(p_xn2, p_WqIn, p_xz, nullptr, BL, 2 * DIN, DM);
    }

    // 5) Causal conv + SiLU
    conv_silu_kernel<<<(BL * DIN + 255) / 256, 256>>>(conv_w, conv_b);

    // 6) dbc = xc @ W_x^T
    dbc_kernel<<<BL, 256>>>(W_x);

    // 7) Selective scan + D skip + gate by silu(z)
    scan_kernel<<<BB * (DIN / 32), 128>>>(dt_w, dt_b, A_log, D_param);

    // 8) RMSNorm on y
    rmsnorm_kernel<6><<<BL, 256>>>(p_y, out_norm_w, p_yn);

    // 9) out = yn @ WqOut^T + residual(x)   [8192 x 768]
    {
        dim3 grid(DM / 128, BL / 128);
        sgemm_kernel<<<grid, 256>>>(p_yn, p_WqOut, out, x, BL, DM, DIN);
    }
}

// round 2
// speedup vs baseline: 1.4105x; 1.4105x over previous
#include <cuda_runtime.h>
#include <cuda_bf16.h>
#include <math.h>
#include <stdint.h>

// Problem dims (fixed for this instance)
#define BB   4
#define LL   2048
#define DM   768
#define DIN  1536
#define NN   16
#define KK   4
#define BL   (BB*LL)          // 8192 tokens

// ----------------------------------------------------------------------------
// Device scratch (static allocations — no cudaMalloc allowed)
// ----------------------------------------------------------------------------
__device__ float g_xn1[BL*DM];                   // rmsnorm(x, norm_w)
__device__ float g_xz [BL*2*DIN];                // bitlinear output [x_path | z]
__device__ float g_xc [BL*DIN];                  // conv + silu
__device__ float g_dbc[BL*33];                   // [dt | B(16) | C(16)]
__device__ float g_y  [BL*DIN];                  // scan output * silu(z)
__device__ __nv_bfloat16 g_A1[BL*2*DM];          // split-bf16 rmsnorm(xn1) [M, 2*DM]
__device__ __nv_bfloat16 g_A2[BL*2*DIN];         // split-bf16 rmsnorm(y)  [M, 2*DIN]
__device__ __nv_bfloat16 g_B1[2*DIN*2*DM];       // ternary W_in duplicated [3072, 1536]
__device__ __nv_bfloat16 g_B2[DM*2*DIN];         // ternary W_out duplicated [768, 3072]
__device__ float g_part[512];                    // reduction partials
__device__ float g_scale[2];                     // scales for W_in / W_out

// ----------------------------------------------------------------------------
// Helpers
// ----------------------------------------------------------------------------
__device__ __forceinline__ float block_reduce_sum(float v, float* sred) {
    #pragma unroll
    for (int s = 16; s; s >>= 1) v += __shfl_xor_sync(0xffffffffu, v, s);
    int w = threadIdx.x >> 5;
    __syncthreads();
    if ((threadIdx.x & 31) == 0) sred[w] = v;
    __syncthreads();
    float t = 0.f;
    int nw = blockDim.x >> 5;
    for (int i = 0; i < nw; i++) t += sred[i];
    return t;
}

__device__ __forceinline__ float silu_f(float x) {
    return x / (1.f + __expf(-x));
}

__device__ __forceinline__ uint32_t cvta_s(const void* p) {
    return (uint32_t)__cvta_generic_to_shared(p);
}

__device__ __forceinline__ void cpa16(uint32_t s, const void* g) {
    asm volatile("cp.async.cg.shared.global [%0], [%1], 16;" :: "r"(s), "l"(g));
}
__device__ __forceinline__ void cpa_commit() {
    asm volatile("cp.async.commit_group;");
}
template <int N_>
__device__ __forceinline__ void cpa_wait() {
    asm volatile("cp.async.wait_group %0;" :: "n"(N_));
}

__device__ __forceinline__ void ldsm4(uint32_t& r0, uint32_t& r1, uint32_t& r2, uint32_t& r3,
                                      uint32_t addr) {
    asm volatile("ldmatrix.sync.aligned.m8n8.x4.shared.b16 {%0,%1,%2,%3}, [%4];"
                 : "=r"(r0), "=r"(r1), "=r"(r2), "=r"(r3) : "r"(addr));
}

__device__ __forceinline__ void mma16816(float* d, const uint32_t* a, const uint32_t* b) {
    asm volatile("mma.sync.aligned.m16n8k16.row.col.f32.bf16.bf16.f32 "
                 "{%0,%1,%2,%3},{%4,%5,%6,%7},{%8,%9},{%0,%1,%2,%3};"
                 : "+f"(d[0]), "+f"(d[1]), "+f"(d[2]), "+f"(d[3])
                 : "r"(a[0]), "r"(a[1]), "r"(a[2]), "r"(a[3]), "r"(b[0]), "r"(b[1]));
}

// ----------------------------------------------------------------------------
// Weight quantization (deterministic 2-phase mean|W|)
// ----------------------------------------------------------------------------
__global__ void abssum_kernel(const float* __restrict__ W, int n, float* __restrict__ part) {
    __shared__ float sred[8];
    float s = 0.f;
    for (int i = blockIdx.x * blockDim.x + threadIdx.x; i < n; i += gridDim.x * blockDim.x)
        s += fabsf(W[i]);
    float tot = block_reduce_sum(s, sred);
    if (threadIdx.x == 0) part[blockIdx.x] = tot;
}

__global__ void finalize_scale_kernel(const float* __restrict__ part, float* __restrict__ scale, float inv_n) {
    __shared__ float sred[8];
    float tot = block_reduce_sum(part[threadIdx.x], sred);
    if (threadIdx.x == 0) *scale = fmaxf(tot * inv_n, 1e-5f);
}

// Ternary quantize -> bf16 {-1,0,1}, duplicated along K: Wb[n][2k]=Wb[n][2k+1]=t
__global__ void quant_bf16_kernel(const float* __restrict__ W, __nv_bfloat16* __restrict__ Wb,
                                  int n, int cols, const float* __restrict__ sp) {
    float scale = *sp;
    for (int i = blockIdx.x * blockDim.x + threadIdx.x; i < n; i += gridDim.x * blockDim.x) {
        float wn = W[i] / scale;
        wn = fminf(fmaxf(wn, -1.f), 1.f);
        float t = rintf(wn);   // round-half-even, matches jnp.round
        int r = i / cols, c = i % cols;
        __nv_bfloat16 tb = __float2bfloat16(t);  // exact: -1/0/1
        size_t o = (size_t)r * (2 * cols) + 2 * c;
        Wb[o] = tb;
        Wb[o + 1] = tb;
    }
}

// ----------------------------------------------------------------------------
// RMSNorm fp32 output (one block per row)
// ----------------------------------------------------------------------------
template <int CNT>
__global__ void rmsnorm_kernel(const float* __restrict__ in, const float* __restrict__ w,
                               float* __restrict__ out) {
    __shared__ float sred[8];
    const int D = CNT * 256;
    size_t base = (size_t)blockIdx.x * D;
    float v[CNT];
    float ss = 0.f;
    #pragma unroll
    for (int i = 0; i < CNT; i++) {
        float x = in[base + threadIdx.x + (i << 8)];
        v[i] = x;
        ss = fmaf(x, x, ss);
    }
    float tot = block_reduce_sum(ss, sred);
    float r = rsqrtf(tot / (float)D + 1e-6f);
    #pragma unroll
    for (int i = 0; i < CNT; i++) {
        int c = threadIdx.x + (i << 8);
        out[base + c] = v[i] * r * w[c];
    }
}

// RMSNorm with split-bf16 output: out[row][2c]=hi(val), out[row][2c+1]=lo(val)
template <int CNT>
__global__ void rmsnorm_split_kernel(const float* __restrict__ in, const float* __restrict__ w,
                                     __nv_bfloat16* __restrict__ out) {
    __shared__ float sred[8];
    const int D = CNT * 256;
    size_t base = (size_t)blockIdx.x * D;
    float v[CNT];
    float ss = 0.f;
    #pragma unroll
    for (int i = 0; i < CNT; i++) {
        float x = in[base + threadIdx.x + (i << 8)];
        v[i] = x;
        ss = fmaf(x, x, ss);
    }
    float tot = block_reduce_sum(ss, sred);
    float r = rsqrtf(tot / (float)D + 1e-6f);
    size_t base2 = (size_t)blockIdx.x * 2 * D;
    #pragma unroll
    for (int i = 0; i < CNT; i++) {
        int c = threadIdx.x + (i << 8);
        float val = v[i] * r * w[c];
        __nv_bfloat16 hi = __float2bfloat16(val);
        __nv_bfloat16 lo = __float2bfloat16(val - __bfloat162float(hi));
        out[base2 + 2 * c]     = hi;
        out[base2 + 2 * c + 1] = lo;
    }
}

// ----------------------------------------------------------------------------
// bf16 tensor-core GEMM: C[M,N] = (A[M,K2] * B[N,K2]^T) * scale (+Res)
// BM=128, BN=128, BK=32. 8 warps, 32x64 warp tiles, mma.m16n8k16.
// Shared rows padded to stride 40 bf16 (conflict-free ldmatrix phases).
// ----------------------------------------------------------------------------
#define LDS_ 40

__global__ __launch_bounds__(256)
void gemm_bf16_kernel(const __nv_bfloat16* __restrict__ A,
                      const __nv_bfloat16* __restrict__ B,
                      float* __restrict__ C, const float* __restrict__ Res,
                      const float* __restrict__ scalep,
                      int M, int N, int K2) {
    __shared__ __align__(16) __nv_bfloat16 sA[2][128 * LDS_];
    __shared__ __align__(16) __nv_bfloat16 sB[2][128 * LDS_];

    int tid  = threadIdx.x;
    int lane = tid & 31;
    int warp = tid >> 5;
    int wm = warp >> 1;          // 0..3  (rows, 32 each)
    int wn = warp & 1;           // 0..1  (cols, 64 each)
    int bm = blockIdx.y * 128;
    int bn = blockIdx.x * 128;

    // ---- loader mapping: 4 x 16B chunks per thread per k-tile
    int r0 = tid >> 2;                  // 0..63
    int c0 = (tid & 3) << 3;            // 0,8,16,24 (bf16 units)
    const __nv_bfloat16* Ag0 = A + (size_t)(bm + r0) * K2 + c0;
    const __nv_bfloat16* Ag1 = A + (size_t)(bm + r0 + 64) * K2 + c0;
    const __nv_bfloat16* Bg0 = B + (size_t)(bn + r0) * K2 + c0;
    const __nv_bfloat16* Bg1 = B + (size_t)(bn + r0 + 64) * K2 + c0;

    uint32_t sAst[2][2], sBst[2][2];
    #pragma unroll
    for (int b = 0; b < 2; b++) {
        sAst[b][0] = cvta_s(&sA[b][(size_t)r0 * LDS_ + c0]);
        sAst[b][1] = cvta_s(&sA[b][(size_t)(r0 + 64) * LDS_ + c0]);
        sBst[b][0] = cvta_s(&sB[b][(size_t)r0 * LDS_ + c0]);
        sBst[b][1] = cvta_s(&sB[b][(size_t)(r0 + 64) * LDS_ + c0]);
    }

    // ---- fragment addressing
    int aRow = wm * 32 + (lane & 15);
    int aCol = (lane >> 4) << 3;
    uint32_t aFrag = (uint32_t)((aRow * LDS_ + aCol) * 2);
    int bRow = wn * 64 + (((lane >> 4) & 1) << 3) + (lane & 7);
    int bCol = ((lane >> 3) & 1) << 3;
    uint32_t bFrag = (uint32_t)((bRow * LDS_ + bCol) * 2);
    uint32_t aBase[2] = {cvta_s(&sA[0][0]), cvta_s(&sA[1][0])};
    uint32_t bBase[2] = {cvta_s(&sB[0][0]), cvta_s(&sB[1][0])};

    float acc[2][8][4];
    #pragma unroll
    for (int i = 0; i < 2; i++)
        #pragma unroll
        for (int j = 0; j < 8; j++)
            #pragma unroll
            for (int k = 0; k < 4; k++) acc[i][j][k] = 0.f;

    int KT = K2 >> 5;

    // prologue: tile 0
    {
        cpa16(sAst[0][0], Ag0); cpa16(sAst[0][1], Ag1);
        cpa16(sBst[0][0], Bg0); cpa16(sBst[0][1], Bg1);
        cpa_commit();
    }

    for (int kt = 0; kt < KT; kt++) {
        int buf = kt & 1;
        if (kt + 1 < KT) {
            int nb = buf ^ 1;
            size_t ko = (size_t)(kt + 1) << 5;
            cpa16(sAst[nb][0], Ag0 + ko); cpa16(sAst[nb][1], Ag1 + ko);
            cpa16(sBst[nb][0], Bg0 + ko); cpa16(sBst[nb][1], Bg1 + ko);
            cpa_commit();
            cpa_wait<1>();
        } else {
            cpa_wait<0>();
        }
        __syncthreads();

        #pragma unroll
        for (int ks = 0; ks < 2; ks++) {
            uint32_t kb = (uint32_t)(ks * 16 * 2);     // byte offset for k0
            uint32_t a[2][4];
            ldsm4(a[0][0], a[0][1], a[0][2], a[0][3], aBase[buf] + aFrag + kb);
            ldsm4(a[1][0], a[1][1], a[1][2], a[1][3], aBase[buf] + aFrag + (16 * LDS_ * 2) + kb);
            uint32_t bf[8][2];
            #pragma unroll
            for (int p = 0; p < 4; p++) {
                ldsm4(bf[2 * p][0], bf[2 * p][1], bf[2 * p + 1][0], bf[2 * p + 1][1],
                      bBase[buf] + bFrag + (uint32_t)(p * 16 * LDS_ * 2) + kb);
            }
            #pragma unroll
            for (int mt = 0; mt < 2; mt++)
                #pragma unroll
                for (int nt = 0; nt < 8; nt++)
                    mma16816(acc[mt][nt], a[mt], bf[nt]);
        }
        __syncthreads();
    }

    // ---- epilogue: *scale (+Res)
    float s = __ldg(scalep);
    int er = bm + wm * 32 + (lane >> 2);
    int ec = bn + wn * 64 + ((lane & 3) << 1);
    #pragma unroll
    for (int mt = 0; mt < 2; mt++) {
        #pragma unroll
        for (int h = 0; h < 2; h++) {
            int row = er + mt * 16 + h * 8;
            #pragma unroll
            for (int nt = 0; nt < 8; nt++) {
                size_t off = (size_t)row * N + ec + nt * 8;
                float2 o;
                o.x = acc[mt][nt][2 * h + 0] * s;
                o.y = acc[mt][nt][2 * h + 1] * s;
                if (Res) {
                    o.x += Res[off];
                    o.y += Res[off + 1];
                }
                *(float2*)(C + off) = o;
            }
        }
    }
}

// ----------------------------------------------------------------------------
// Causal depthwise conv (K=4) + bias + SiLU, reading x_path slice from g_xz
// ----------------------------------------------------------------------------
__global__ void conv_silu_kernel(const float* __restrict__ cw, const float* __restrict__ cb) {
    int idx = blockIdx.x * blockDim.x + threadIdx.x;
    if (idx >= BL * DIN) return;
    int d = idx % DIN;
    int m = idx / DIN;       // b*L + l
    int l = m & (LL - 1);
    float acc = cb[d];
    #pragma unroll
    for (int k = 0; k < KK; k++) {
        int ll = l + k - (KK - 1);
        if (ll >= 0)
            acc = fmaf(g_xz[(size_t)(m + k - (KK - 1)) * (2 * DIN) + d], cw[d * KK + k], acc);
    }
    g_xc[(size_t)m * DIN + d] = silu_f(acc);
}

// ----------------------------------------------------------------------------
// dbc = xc @ W_x^T   (N_out = 33)
// ----------------------------------------------------------------------------
__global__ void dbc_kernel(const float* __restrict__ Wx) {
    int m = blockIdx.x;
    int warp = threadIdx.x >> 5, lane = threadIdx.x & 31;
    const float4* row = (const float4*)(g_xc + (size_t)m * DIN);
    for (int o = warp; o < 33; o += 8) {
        const float4* w = (const float4*)(Wx + (size_t)o * DIN);
        float acc = 0.f;
        for (int q = lane; q < DIN / 4; q += 32) {
            float4 xv = row[q], wv = w[q];
            acc = fmaf(xv.x, wv.x, fmaf(xv.y, wv.y, fmaf(xv.z, wv.z, fmaf(xv.w, wv.w, acc))));
        }
        #pragma unroll
        for (int s = 16; s; s >>= 1) acc += __shfl_xor_sync(0xffffffffu, acc, s);
        if (!lane) g_dbc[m * 33 + o] = acc;
    }
}

// ----------------------------------------------------------------------------
// Selective scan + D skip + gate by silu(z)
// ----------------------------------------------------------------------------
__global__ void scan_kernel(const float* __restrict__ dt_w, const float* __restrict__ dt_b,
                            const float* __restrict__ A_log, const float* __restrict__ D_param) {
    const int DPB = 32;
    int b    = blockIdx.x / (DIN / DPB);
    int dblk = blockIdx.x % (DIN / DPB);
    int ng   = threadIdx.x & 3;
    int dloc = threadIdx.x >> 2;
    int d = dblk * DPB + dloc;

    float A4[4], h[4];
    #pragma unroll
    for (int j = 0; j < 4; j++) {
        A4[j] = -expf(A_log[d * NN + ng * 4 + j]);
        h[j] = 0.f;
    }
    float dtw = dt_w[d], dtb = dt_b[d], Dp = D_param[d];
    size_t mbase = (size_t)b * LL;

    for (int l = 0; l < LL; l++) {
        size_t m = mbase + l;
        const float* dbc = g_dbc + m * 33;
        float dt = __ldg(dbc);
        float sp_in = fmaf(dt, dtw, dtb);
        float delta = (sp_in > 20.f) ? sp_in : log1pf(__expf(sp_in));
        float u  = g_xc[m * DIN + d];
        float du = delta * u;
        float y = 0.f;
        #pragma unroll
        for (int j = 0; j < 4; j++) {
            int n = ng * 4 + j;
            float dA = __expf(delta * A4[j]);
            h[j] = fmaf(dA, h[j], du * __ldg(dbc + 1 + n));
            y = fmaf(h[j], __ldg(dbc + 17 + n), y);
        }
        y += __shfl_xor_sync(0xffffffffu, y, 1);
        y += __shfl_xor_sync(0xffffffffu, y, 2);
        if (ng == 0) {
            float yy = fmaf(u, Dp, y);
            float z = g_xz[m * (2 * DIN) + DIN + d];
            g_y[m * DIN + d] = yy * silu_f(z);
        }
    }
}

// ----------------------------------------------------------------------------
// Launch
// ----------------------------------------------------------------------------
extern "C" void kernel_launch(void* const* d_in, const int* in_sizes, int n_in,
                              void* d_out, int out_size) {
    const float* x         = (const float*)d_in[0];
    const float* norm_w    = (const float*)d_in[1];
    const float* in_norm_w = (const float*)d_in[2];
    const float* W_in      = (const float*)d_in[3];
    const float* conv_w    = (const float*)d_in[4];
    const float* conv_b    = (const float*)d_in[5];
    const float* W_x       = (const float*)d_in[6];
    const float* dt_w      = (const float*)d_in[7];
    const float* dt_b      = (const float*)d_in[8];
    const float* A_log     = (const float*)d_in[9];
    const float* D_param   = (const float*)d_in[10];
    const float* out_norm_w = (const float*)d_in[11];
    const float* W_out      = (const float*)d_in[12];
    float* out = (float*)d_out;

    float *p_xn1, *p_xz, *p_y, *p_part, *p_scale;
    __nv_bfloat16 *p_A1, *p_A2, *p_B1, *p_B2;
    cudaGetSymbolAddress((void**)&p_xn1,   g_xn1);
    cudaGetSymbolAddress((void**)&p_xz,    g_xz);
    cudaGetSymbolAddress((void**)&p_y,     g_y);
    cudaGetSymbolAddress((void**)&p_part,  g_part);
    cudaGetSymbolAddress((void**)&p_scale, g_scale);
    cudaGetSymbolAddress((void**)&p_A1,    g_A1);
    cudaGetSymbolAddress((void**)&p_A2,    g_A2);
    cudaGetSymbolAddress((void**)&p_B1,    g_B1);
    cudaGetSymbolAddress((void**)&p_B2,    g_B2);

    const int nWin  = 2 * DIN * DM;   // 2359296
    const int nWout = DM * DIN;       // 1179648

    // 1) Weight scales (deterministic two-phase)
    abssum_kernel<<<256, 256>>>(W_in,  nWin,  p_part);
    abssum_kernel<<<256, 256>>>(W_out, nWout, p_part + 256);
    finalize_scale_kernel<<<1, 256>>>(p_part,       p_scale,     1.f / (float)nWin);
    finalize_scale_kernel<<<1, 256>>>(p_part + 256, p_scale + 1, 1.f / (float)nWout);

    // 2) Ternary-quantize weights to bf16 (K-duplicated); scale applied in GEMM epilogue
    quant_bf16_kernel<<<2048, 256>>>(W_in,  p_B1, nWin,  DM,  p_scale);
    quant_bf16_kernel<<<2048, 256>>>(W_out, p_B2, nWout, DIN, p_scale + 1);

    // 3) RMSNorm x -> xn1 (fp32), then RMSNorm xn1 -> split-bf16 A1
    rmsnorm_kernel<3><<<BL, 256>>>(x, norm_w, p_xn1);
    rmsnorm_split_kernel<3><<<BL, 256>>>(p_xn1, in_norm_w, p_A1);

    // 4) xz = (A1 @ B1^T) * scale0   [8192 x 3072], K2=1536
    {
        dim3 grid(2 * DIN / 128, BL / 128);
        gemm_bf16_kernel<<<grid, 256>>>(p_A1, p_B1, p_xz, nullptr, p_scale, BL, 2 * DIN, 2 * DM);
    }

    // 5) Causal conv + SiLU
    conv_silu_kernel<<<(BL * DIN + 255) / 256, 256>>>(conv_w, conv_b);

    // 6) dbc = xc @ W_x^T
    dbc_kernel<<<BL, 256>>>(W_x);

    // 7) Selective scan + D skip + gate by silu(z)
    scan_kernel<<<BB * (DIN / 32), 128>>>(dt_w, dt_b, A_log, D_param);

    // 8) RMSNorm y -> split-bf16 A2
    rmsnorm_split_kernel<6><<<BL, 256>>>(p_y, out_norm_w, p_A2);

    // 9) out = (A2 @ B2^T) * scale1 + residual(x)   [8192 x 768], K2=3072
    {
        dim3 grid(DM / 128, BL / 128);
        gemm_bf16_kernel<<<grid, 256>>>(p_A2, p_B2, out, x, p_scale + 1, BL, DM, 2 * DIN);
    }
}

// round 3
// speedup vs baseline: 3.4490x; 2.4452x over previous
#include <cuda_runtime.h>
#include <cuda_bf16.h>
#include <math.h>
#include <stdint.h>

// Problem dims (fixed for this instance)
#define BB   4
#define LL   2048
#define DM   768
#define DIN  1536
#define NN   16
#define KK   4
#define BL   (BB*LL)          // 8192 tokens
#define CH   8                // scan chunks
#define CLEN (LL/CH)          // 256

// ----------------------------------------------------------------------------
// Device scratch
// ----------------------------------------------------------------------------
__device__ float g_xz [BL*2*DIN];                // bitlinear output [x_path | z]
__device__ float g_xc [BL*DIN];                  // conv + silu
__device__ float g_dbc[BL*33];                   // [dt | B(16) | C(16)]
__device__ float g_y  [BL*DIN];                  // scan output * silu(z)
__device__ __nv_bfloat16 g_A1[BL*2*DM];          // split-bf16 rmsnorm2(x) [M, 2*DM]
__device__ __nv_bfloat16 g_A2[BL*2*DIN];         // split-bf16 rmsnorm(y)  [M, 2*DIN]
__device__ __nv_bfloat16 g_B1[2*DIN*2*DM];       // ternary W_in duplicated [3072, 1536]
__device__ __nv_bfloat16 g_B2[DM*2*DIN];         // ternary W_out duplicated [768, 3072]
__device__ float g_carry[BB*CH*DIN*NN];          // chunk carries / h_in (in-place)
__device__ float g_sumd [BB*CH*DIN];             // per-chunk sum of delta
__device__ float g_part[512];                    // reduction partials
__device__ float g_scale[2];                     // scales for W_in / W_out

// ----------------------------------------------------------------------------
// Helpers
// ----------------------------------------------------------------------------
__device__ __forceinline__ float block_reduce_sum(float v, float* sred) {
    #pragma unroll
    for (int s = 16; s; s >>= 1) v += __shfl_xor_sync(0xffffffffu, v, s);
    int w = threadIdx.x >> 5;
    __syncthreads();
    if ((threadIdx.x & 31) == 0) sred[w] = v;
    __syncthreads();
    float t = 0.f;
    int nw = blockDim.x >> 5;
    for (int i = 0; i < nw; i++) t += sred[i];
    return t;
}

__device__ __forceinline__ float silu_f(float x) {
    return x / (1.f + __expf(-x));
}

__device__ __forceinline__ uint32_t cvta_s(const void* p) {
    return (uint32_t)__cvta_generic_to_shared(p);
}

__device__ __forceinline__ void cpa16(uint32_t s, const void* g) {
    asm volatile("cp.async.cg.shared.global [%0], [%1], 16;" :: "r"(s), "l"(g));
}
__device__ __forceinline__ void cpa_commit() {
    asm volatile("cp.async.commit_group;");
}
template <int N_>
__device__ __forceinline__ void cpa_wait() {
    asm volatile("cp.async.wait_group %0;" :: "n"(N_));
}

__device__ __forceinline__ void ldsm4(uint32_t& r0, uint32_t& r1, uint32_t& r2, uint32_t& r3,
                                      uint32_t addr) {
    asm volatile("ldmatrix.sync.aligned.m8n8.x4.shared.b16 {%0,%1,%2,%3}, [%4];"
                 : "=r"(r0), "=r"(r1), "=r"(r2), "=r"(r3) : "r"(addr));
}

__device__ __forceinline__ void mma16816(float* d, const uint32_t* a, const uint32_t* b) {
    asm volatile("mma.sync.aligned.m16n8k16.row.col.f32.bf16.bf16.f32 "
                 "{%0,%1,%2,%3},{%4,%5,%6,%7},{%8,%9},{%0,%1,%2,%3};"
                 : "+f"(d[0]), "+f"(d[1]), "+f"(d[2]), "+f"(d[3])
                 : "r"(a[0]), "r"(a[1]), "r"(a[2]), "r"(a[3]), "r"(b[0]), "r"(b[1]));
}

// ----------------------------------------------------------------------------
// Weight quantization (deterministic 2-phase mean|W|)
// ----------------------------------------------------------------------------
__global__ void abssum_kernel(const float* __restrict__ W, int n, float* __restrict__ part) {
    __shared__ float sred[8];
    float s = 0.f;
    for (int i = blockIdx.x * blockDim.x + threadIdx.x; i < n; i += gridDim.x * blockDim.x)
        s += fabsf(W[i]);
    float tot = block_reduce_sum(s, sred);
    if (threadIdx.x == 0) part[blockIdx.x] = tot;
}

__global__ void finalize_scale_kernel(const float* __restrict__ part, float* __restrict__ scale, float inv_n) {
    __shared__ float sred[8];
    float tot = block_reduce_sum(part[threadIdx.x], sred);
    if (threadIdx.x == 0) *scale = fmaxf(tot * inv_n, 1e-5f);
}

// Ternary quantize -> bf16 {-1,0,1}, duplicated along K
__global__ void quant_bf16_kernel(const float* __restrict__ W, __nv_bfloat16* __restrict__ Wb,
                                  int n, int cols, const float* __restrict__ sp) {
    float scale = *sp;
    for (int i = blockIdx.x * blockDim.x + threadIdx.x; i < n; i += gridDim.x * blockDim.x) {
        float wn = W[i] / scale;
        wn = fminf(fmaxf(wn, -1.f), 1.f);
        float t = rintf(wn);
        int r = i / cols, c = i % cols;
        __nv_bfloat16 tb = __float2bfloat16(t);
        size_t o = (size_t)r * (2 * cols) + 2 * c;
        Wb[o] = tb;
        Wb[o + 1] = tb;
    }
}

// ----------------------------------------------------------------------------
// Fused double RMSNorm (x -> rmsnorm(w1) -> rmsnorm(w2)) with split-bf16 out
// ----------------------------------------------------------------------------
__global__ void rmsnorm2_split_kernel(const float* __restrict__ in,
                                      const float* __restrict__ w1,
                                      const float* __restrict__ w2,
                                      __nv_bfloat16* __restrict__ out) {
    __shared__ float sred[8];
    const int D = 768;
    size_t base = (size_t)blockIdx.x * D;
    float v[3], t[3];
    float ss = 0.f;
    #pragma unroll
    for (int i = 0; i < 3; i++) {
        float x = in[base + threadIdx.x + (i << 8)];
        v[i] = x;
        ss = fmaf(x, x, ss);
    }
    float tot = block_reduce_sum(ss, sred);
    float r1 = rsqrtf(tot / (float)D + 1e-6f);
    float ss2 = 0.f;
    #pragma unroll
    for (int i = 0; i < 3; i++) {
        int c = threadIdx.x + (i << 8);
        t[i] = v[i] * r1 * w1[c];
        ss2 = fmaf(t[i], t[i], ss2);
    }
    float tot2 = block_reduce_sum(ss2, sred);
    float r2 = rsqrtf(tot2 / (float)D + 1e-6f);
    size_t base2 = (size_t)blockIdx.x * 2 * D;
    #pragma unroll
    for (int i = 0; i < 3; i++) {
        int c = threadIdx.x + (i << 8);
        float val = t[i] * r2 * w2[c];
        __nv_bfloat16 hi = __float2bfloat16(val);
        __nv_bfloat16 lo = __float2bfloat16(val - __bfloat162float(hi));
        out[base2 + 2 * c]     = hi;
        out[base2 + 2 * c + 1] = lo;
    }
}

// Single RMSNorm with split-bf16 output (for y, D = 1536)
template <int CNT>
__global__ void rmsnorm_split_kernel(const float* __restrict__ in, const float* __restrict__ w,
                                     __nv_bfloat16* __restrict__ out) {
    __shared__ float sred[8];
    const int D = CNT * 256;
    size_t base = (size_t)blockIdx.x * D;
    float v[CNT];
    float ss = 0.f;
    #pragma unroll
    for (int i = 0; i < CNT; i++) {
        float x = in[base + threadIdx.x + (i << 8)];
        v[i] = x;
        ss = fmaf(x, x, ss);
    }
    float tot = block_reduce_sum(ss, sred);
    float r = rsqrtf(tot / (float)D + 1e-6f);
    size_t base2 = (size_t)blockIdx.x * 2 * D;
    #pragma unroll
    for (int i = 0; i < CNT; i++) {
        int c = threadIdx.x + (i << 8);
        float val = v[i] * r * w[c];
        __nv_bfloat16 hi = __float2bfloat16(val);
        __nv_bfloat16 lo = __float2bfloat16(val - __bfloat162float(hi));
        out[base2 + 2 * c]     = hi;
        out[base2 + 2 * c + 1] = lo;
    }
}

// ----------------------------------------------------------------------------
// bf16 tensor-core GEMM: C[M,N] = (A[M,K2] * B[N,K2]^T) * scale (+Res)
// BM=128, BN=128, BK=32, 3-stage cp.async pipeline, one sync per k-tile.
// ----------------------------------------------------------------------------
#define LDS_   40
#define TILEE  (128 * LDS_)     // bf16 elems per stage per matrix
#define GSTG   3
#define GEMM_SMEM (GSTG * TILEE * 2 * 2)  // bytes

__global__ __launch_bounds__(256)
void gemm_bf16_kernel(const __nv_bfloat16* __restrict__ A,
                      const __nv_bfloat16* __restrict__ B,
                      float* __restrict__ C, const float* __restrict__ Res,
                      const float* __restrict__ scalep,
                      int M, int N, int K2) {
    extern __shared__ __nv_bfloat16 smem_[];
    __nv_bfloat16* sA = smem_;
    __nv_bfloat16* sB = smem_ + GSTG * TILEE;

    int tid  = threadIdx.x;
    int lane = tid & 31;
    int warp = tid >> 5;
    int wm = warp >> 1;
    int wn = warp & 1;
    int bm = blockIdx.y * 128;
    int bn = blockIdx.x * 128;

    int r0 = tid >> 2;
    int c0 = (tid & 3) << 3;
    const __nv_bfloat16* Ag0 = A + (size_t)(bm + r0) * K2 + c0;
    const __nv_bfloat16* Ag1 = A + (size_t)(bm + r0 + 64) * K2 + c0;
    const __nv_bfloat16* Bg0 = B + (size_t)(bn + r0) * K2 + c0;
    const __nv_bfloat16* Bg1 = B + (size_t)(bn + r0 + 64) * K2 + c0;

    uint32_t sAbase = cvta_s(sA);
    uint32_t sBbase = cvta_s(sB);
    uint32_t st0 = (uint32_t)((r0 * LDS_ + c0) * 2);
    uint32_t st1 = st0 + (uint32_t)(64 * LDS_ * 2);

    int aRow = wm * 32 + (lane & 15);
    int aCol = (lane >> 4) << 3;
    uint32_t aFrag = (uint32_t)((aRow * LDS_ + aCol) * 2);
    int bRow = wn * 64 + (((lane >> 4) & 1) << 3) + (lane & 7);
    int bCol = ((lane >> 3) & 1) << 3;
    uint32_t bFrag = (uint32_t)((bRow * LDS_ + bCol) * 2);

    float acc[2][8][4];
    #pragma unroll
    for (int i = 0; i < 2; i++)
        #pragma unroll
        for (int j = 0; j < 8; j++)
            #pragma unroll
            for (int k = 0; k < 4; k++) acc[i][j][k] = 0.f;

    int KT = K2 >> 5;

    // prologue: issue tiles 0 and 1 into stages 0 and 1
    #pragma unroll
    for (int t = 0; t < 2; t++) {
        size_t ko = (size_t)t << 5;
        uint32_t ao = sAbase + (uint32_t)(t * TILEE * 2);
        uint32_t bo = sBbase + (uint32_t)(t * TILEE * 2);
        cpa16(ao + st0, Ag0 + ko); cpa16(ao + st1, Ag1 + ko);
        cpa16(bo + st0, Bg0 + ko); cpa16(bo + st1, Bg1 + ko);
        cpa_commit();
    }

    int s = 0;
    for (int kt = 0; kt < KT; kt++) {
        if (kt == KT - 1) cpa_wait<0>(); else cpa_wait<1>();
        __syncthreads();
        if (kt + 2 < KT) {
            int sn = s + 2; if (sn >= GSTG) sn -= GSTG;
            size_t ko = (size_t)(kt + 2) << 5;
            uint32_t ao = sAbase + (uint32_t)(sn * TILEE * 2);
            uint32_t bo = sBbase + (uint32_t)(sn * TILEE * 2);
            cpa16(ao + st0, Ag0 + ko); cpa16(ao + st1, Ag1 + ko);
            cpa16(bo + st0, Bg0 + ko); cpa16(bo + st1, Bg1 + ko);
            cpa_commit();
        }

        uint32_t aS = sAbase + (uint32_t)(s * TILEE * 2) + aFrag;
        uint32_t bS = sBbase + (uint32_t)(s * TILEE * 2) + bFrag;
        #pragma unroll
        for (int ks = 0; ks < 2; ks++) {
            uint32_t kb = (uint32_t)(ks * 16 * 2);
            uint32_t a[2][4];
            ldsm4(a[0][0], a[0][1], a[0][2], a[0][3], aS + kb);
            ldsm4(a[1][0], a[1][1], a[1][2], a[1][3], aS + (16 * LDS_ * 2) + kb);
            uint32_t bf[8][2];
            #pragma unroll
            for (int p = 0; p < 4; p++) {
                ldsm4(bf[2 * p][0], bf[2 * p][1], bf[2 * p + 1][0], bf[2 * p + 1][1],
                      bS + (uint32_t)(p * 16 * LDS_ * 2) + kb);
            }
            #pragma unroll
            for (int mt = 0; mt < 2; mt++)
                #pragma unroll
                for (int nt = 0; nt < 8; nt++)
                    mma16816(acc[mt][nt], a[mt], bf[nt]);
        }
        s++; if (s >= GSTG) s = 0;
    }

    float sc = __ldg(scalep);
    int er = bm + wm * 32 + (lane >> 2);
    int ec = bn + wn * 64 + ((lane & 3) << 1);
    #pragma unroll
    for (int mt = 0; mt < 2; mt++) {
        #pragma unroll
        for (int h = 0; h < 2; h++) {
            int row = er + mt * 16 + h * 8;
            #pragma unroll
            for (int nt = 0; nt < 8; nt++) {
                size_t off = (size_t)row * N + ec + nt * 8;
                float2 o;
                o.x = acc[mt][nt][2 * h + 0] * sc;
                o.y = acc[mt][nt][2 * h + 1] * sc;
                if (Res) {
                    o.x += Res[off];
                    o.y += Res[off + 1];
                }
                *(float2*)(C + off) = o;
            }
        }
    }
}

// ----------------------------------------------------------------------------
// Causal depthwise conv (K=4) + bias + SiLU — 4 tokens per thread
// ----------------------------------------------------------------------------
__global__ void conv_silu_kernel(const float* __restrict__ cw, const float* __restrict__ cb) {
    int idx = blockIdx.x * blockDim.x + threadIdx.x;
    const int TOT = (BL / 4) * DIN;
    if (idx >= TOT) return;
    int d = idx % DIN;
    int q = idx / DIN;
    int m0 = q << 2;
    int l0 = m0 & (LL - 1);
    float w0 = cw[d * 4], w1 = cw[d * 4 + 1], w2 = cw[d * 4 + 2], w3 = cw[d * 4 + 3];
    float bias = cb[d];
    float xw[7];
    #pragma unroll
    for (int i = 0; i < 7; i++) {
        int l = l0 + i - 3;
        xw[i] = (l >= 0) ? g_xz[(size_t)(m0 + i - 3) * (2 * DIN) + d] : 0.f;
    }
    #pragma unroll
    for (int t = 0; t < 4; t++) {
        float acc = bias;
        acc = fmaf(xw[t],     w0, acc);
        acc = fmaf(xw[t + 1], w1, acc);
        acc = fmaf(xw[t + 2], w2, acc);
        acc = fmaf(xw[t + 3], w3, acc);
        g_xc[(size_t)(m0 + t) * DIN + d] = silu_f(acc);
    }
}

// ----------------------------------------------------------------------------
// dbc = xc @ W_x^T  — tiled GEMM (BM=64 tokens, all 33 outputs, BK=64)
// ----------------------------------------------------------------------------
__global__ __launch_bounds__(256)
void dbc_kernel(const float* __restrict__ Wx) {
    __shared__ float sA[64][65];
    __shared__ float sB[33][65];
    int tid = threadIdx.x;
    int m0 = blockIdx.x * 64;
    int row = tid >> 2;
    int og  = tid & 3;
    float acc[9];
    #pragma unroll
    for (int j = 0; j < 9; j++) acc[j] = 0.f;

    for (int k0 = 0; k0 < DIN; k0 += 64) {
        #pragma unroll
        for (int i = tid; i < 64 * 16; i += 256) {
            int r = i >> 4;
            int c4 = (i & 15) << 2;
            float4 v = *(const float4*)(g_xc + (size_t)(m0 + r) * DIN + k0 + c4);
            sA[r][c4] = v.x; sA[r][c4 + 1] = v.y; sA[r][c4 + 2] = v.z; sA[r][c4 + 3] = v.w;
        }
        for (int i = tid; i < 33 * 16; i += 256) {
            int r = i >> 4;
            int c4 = (i & 15) << 2;
            float4 v = *(const float4*)(Wx + (size_t)r * DIN + k0 + c4);
            sB[r][c4] = v.x; sB[r][c4 + 1] = v.y; sB[r][c4 + 2] = v.z; sB[r][c4 + 3] = v.w;
        }
        __syncthreads();
        #pragma unroll 8
        for (int kk = 0; kk < 64; kk++) {
            float a = sA[row][kk];
            #pragma unroll
            for (int j = 0; j < 9; j++) {
                int o = og + 4 * j;
                if (o < 33) acc[j] = fmaf(a, sB[o][kk], acc[j]);
            }
        }
        __syncthreads();
    }
    #pragma unroll
    for (int j = 0; j < 9; j++) {
        int o = og + 4 * j;
        if (o < 33) g_dbc[(size_t)(m0 + row) * 33 + o] = acc[j];
    }
}

// ----------------------------------------------------------------------------
// Chunked selective scan
// ----------------------------------------------------------------------------
// Phase 1: per-chunk local scan (h0=0), store final h + sum(delta)
__global__ void scan_phase1(const float* __restrict__ dt_w, const float* __restrict__ dt_b,
                            const float* __restrict__ A_log) {
    int blk = blockIdx.x;
    int dblk = blk % (DIN / 32);
    int tmp = blk / (DIN / 32);
    int c = tmp % CH;
    int b = tmp / CH;
    int ng = threadIdx.x & 3;
    int dloc = threadIdx.x >> 2;
    int d = dblk * 32 + dloc;

    float A4[4], h[4];
    #pragma unroll
    for (int j = 0; j < 4; j++) {
        A4[j] = -expf(A_log[d * NN + ng * 4 + j]);
        h[j] = 0.f;
    }
    float dtw = dt_w[d], dtb = dt_b[d];
    float sumdelta = 0.f;
    size_t mbase = (size_t)b * LL + (size_t)c * CLEN;

    for (int l = 0; l < CLEN; l++) {
        size_t m = mbase + l;
        const float* dbc = g_dbc + m * 33;
        float dt = __ldg(dbc);
        float sp_in = fmaf(dt, dtw, dtb);
        float delta = (sp_in > 20.f) ? sp_in : log1pf(__expf(sp_in));
        sumdelta += delta;
        float u  = g_xc[m * DIN + d];
        float du = delta * u;
        #pragma unroll
        for (int j = 0; j < 4; j++) {
            float dA = __expf(delta * A4[j]);
            h[j] = fmaf(dA, h[j], du * __ldg(dbc + 1 + ng * 4 + j));
        }
    }
    size_t base = (((size_t)(b * CH + c)) * DIN + d) * NN + ng * 4;
    float4 st; st.x = h[0]; st.y = h[1]; st.z = h[2]; st.w = h[3];
    *(float4*)(g_carry + base) = st;
    if (ng == 0) g_sumd[(b * CH + c) * DIN + d] = sumdelta;
}

// Phase 2: sequential carry scan over CH chunks (in-place: carry -> h_in)
__global__ void scan_phase2(const float* __restrict__ A_log) {
    int idx = blockIdx.x * blockDim.x + threadIdx.x;
    if (idx >= BB * DIN * NN) return;
    int n = idx % NN;
    int d = (idx / NN) % DIN;
    int b = idx / (NN * DIN);
    float A = -expf(A_log[d * NN + n]);
    float h = 0.f;
    #pragma unroll
    for (int c = 0; c < CH; c++) {
        size_t o = (((size_t)(b * CH + c)) * DIN + d) * NN + n;
        float loc = g_carry[o];
        g_carry[o] = h;
        float P = __expf(A * g_sumd[(b * CH + c) * DIN + d]);
        h = fmaf(P, h, loc);
    }
}

// Phase 3: re-scan with correct h_in, emit y = (scan + u*D) * silu(z)
__global__ void scan_phase3(const float* __restrict__ dt_w, const float* __restrict__ dt_b,
                            const float* __restrict__ A_log, const float* __restrict__ D_param) {
    int blk = blockIdx.x;
    int dblk = blk % (DIN / 32);
    int tmp = blk / (DIN / 32);
    int c = tmp % CH;
    int b = tmp / CH;
    int ng = threadIdx.x & 3;
    int dloc = threadIdx.x >> 2;
    int d = dblk * 32 + dloc;

    float A4[4], h[4];
    size_t cbase = (((size_t)(b * CH + c)) * DIN + d) * NN + ng * 4;
    float4 h0 = *(const float4*)(g_carry + cbase);
    h[0] = h0.x; h[1] = h0.y; h[2] = h0.z; h[3] = h0.w;
    #pragma unroll
    for (int j = 0; j < 4; j++)
        A4[j] = -expf(A_log[d * NN + ng * 4 + j]);

    float dtw = dt_w[d], dtb = dt_b[d], Dp = D_param[d];
    size_t mbase = (size_t)b * LL + (size_t)c * CLEN;

    for (int l = 0; l < CLEN; l++) {
        size_t m = mbase + l;
        const float* dbc = g_dbc + m * 33;
        float dt = __ldg(dbc);
        float sp_in = fmaf(dt, dtw, dtb);
        float delta = (sp_in > 20.f) ? sp_in : log1pf(__expf(sp_in));
        float u  = g_xc[m * DIN + d];
        float du = delta * u;
        float y = 0.f;
        #pragma unroll
        for (int j = 0; j < 4; j++) {
            int n = ng * 4 + j;
            float dA = __expf(delta * A4[j]);
            h[j] = fmaf(dA, h[j], du * __ldg(dbc + 1 + n));
            y = fmaf(h[j], __ldg(dbc + 17 + n), y);
        }
        y += __shfl_xor_sync(0xffffffffu, y, 1);
        y += __shfl_xor_sync(0xffffffffu, y, 2);
        if (ng == 0) {
            float yy = fmaf(u, Dp, y);
            float z = g_xz[m * (2 * DIN) + DIN + d];
            g_y[m * DIN + d] = yy * silu_f(z);
        }
    }
}

// ----------------------------------------------------------------------------
// Launch
// ----------------------------------------------------------------------------
extern "C" void kernel_launch(void* const* d_in, const int* in_sizes, int n_in,
                              void* d_out, int out_size) {
    const float* x         = (const float*)d_in[0];
    const float* norm_w    = (const float*)d_in[1];
    const float* in_norm_w = (const float*)d_in[2];
    const float* W_in      = (const float*)d_in[3];
    const float* conv_w    = (const float*)d_in[4];
    const float* conv_b    = (const float*)d_in[5];
    const float* W_x       = (const float*)d_in[6];
    const float* dt_w      = (const float*)d_in[7];
    const float* dt_b      = (const float*)d_in[8];
    const float* A_log     = (const float*)d_in[9];
    const float* D_param   = (const float*)d_in[10];
    const float* out_norm_w = (const float*)d_in[11];
    const float* W_out      = (const float*)d_in[12];
    float* out = (float*)d_out;

    float *p_xz, *p_y, *p_part, *p_scale;
    __nv_bfloat16 *p_A1, *p_A2, *p_B1, *p_B2;
    cudaGetSymbolAddress((void**)&p_xz,    g_xz);
    cudaGetSymbolAddress((void**)&p_y,     g_y);
    cudaGetSymbolAddress((void**)&p_part,  g_part);
    cudaGetSymbolAddress((void**)&p_scale, g_scale);
    cudaGetSymbolAddress((void**)&p_A1,    g_A1);
    cudaGetSymbolAddress((void**)&p_A2,    g_A2);
    cudaGetSymbolAddress((void**)&p_B1,    g_B1);
    cudaGetSymbolAddress((void**)&p_B2,    g_B2);

    cudaFuncSetAttribute(gemm_bf16_kernel, cudaFuncAttributeMaxDynamicSharedMemorySize, GEMM_SMEM);

    const int nWin  = 2 * DIN * DM;   // 2359296
    const int nWout = DM * DIN;       // 1179648

    // 1) Weight scales
    abssum_kernel<<<256, 256>>>(W_in,  nWin,  p_part);
    abssum_kernel<<<256, 256>>>(W_out, nWout, p_part + 256);
    finalize_scale_kernel<<<1, 256>>>(p_part,       p_scale,     1.f / (float)nWin);
    finalize_scale_kernel<<<1, 256>>>(p_part + 256, p_scale + 1, 1.f / (float)nWout);

    // 2) Ternary-quantize weights to bf16 (K-duplicated)
    quant_bf16_kernel<<<2048, 256>>>(W_in,  p_B1, nWin,  DM,  p_scale);
    quant_bf16_kernel<<<2048, 256>>>(W_out, p_B2, nWout, DIN, p_scale + 1);

    // 3) Fused double RMSNorm x -> split-bf16 A1
    rmsnorm2_split_kernel<<<BL, 256>>>(x, norm_w, in_norm_w, p_A1);

    // 4) xz = (A1 @ B1^T) * scale0
    {
        dim3 grid(2 * DIN / 128, BL / 128);
        gemm_bf16_kernel<<<grid, 256, GEMM_SMEM>>>(p_A1, p_B1, p_xz, nullptr, p_scale, BL, 2 * DIN, 2 * DM);
    }

    // 5) Causal conv + SiLU (4 tokens/thread)
    conv_silu_kernel<<<((BL / 4) * DIN + 255) / 256, 256>>>(conv_w, conv_b);

    // 6) dbc = xc @ W_x^T (tiled)
    dbc_kernel<<<BL / 64, 256>>>(W_x);

    // 7) Chunked selective scan
    scan_phase1<<<BB * CH * (DIN / 32), 128>>>(dt_w, dt_b, A_log);
    scan_phase2<<<(BB * DIN * NN + 255) / 256, 256>>>(A_log);
    scan_phase3<<<BB * CH * (DIN / 32), 128>>>(dt_w, dt_b, A_log, D_param);

    // 8) RMSNorm y -> split-bf16 A2
    rmsnorm_split_kernel<6><<<BL, 256>>>(p_y, out_norm_w, p_A2);

    // 9) out = (A2 @ B2^T) * scale1 + residual(x)
    {
        dim3 grid(DM / 128, BL / 128);
        gemm_bf16_kernel<<<grid, 256, GEMM_SMEM>>>(p_A2, p_B2, out, x, p_scale + 1, BL, DM, 2 * DIN);
    }
}

// round 5
// speedup vs baseline: 4.2060x; 1.2195x over previous
#include <cuda_runtime.h>
#include <cuda_fp16.h>
#include <math.h>
#include <stdint.h>

// Problem dims (fixed for this instance)
#define BB   4
#define LL   2048
#define DM   768
#define DIN  1536
#define NN   16
#define KK   4
#define BL   (BB*LL)          // 8192 tokens
#define CH   8                // scan chunks
#define CLEN (LL/CH)          // 256

// ----------------------------------------------------------------------------
// Device scratch
// ----------------------------------------------------------------------------
__device__ float g_xz [BL*2*DIN];                // bitlinear output [x_path | z]
__device__ float g_xc [BL*DIN];                  // conv + silu
__device__ float g_dbc[BL*33];                   // [dt | B(16) | C(16)]
__device__ float g_y  [BL*DIN];                  // scan output * silu(z)
__device__ __half g_A1[BL*DM];                   // fp16 rmsnorm2(x) [M, DM]
__device__ __half g_A2[BL*DIN];                  // fp16 rmsnorm(y)  [M, DIN]
__device__ __half g_B1[2*DIN*DM];                // ternary W_in  fp16 [3072, 768]
__device__ __half g_B2[DM*DIN];                  // ternary W_out fp16 [768, 1536]
__device__ float g_carry[BB*CH*DIN*NN];          // chunk carries / h_in (in-place)
__device__ float g_sumd [BB*CH*DIN];             // per-chunk sum of delta
__device__ float g_part[512];                    // reduction partials
__device__ float g_scale[2];                     // scales for W_in / W_out

// ----------------------------------------------------------------------------
// Helpers
// ----------------------------------------------------------------------------
__device__ __forceinline__ float block_reduce_sum(float v, float* sred) {
    #pragma unroll
    for (int s = 16; s; s >>= 1) v += __shfl_xor_sync(0xffffffffu, v, s);
    int w = threadIdx.x >> 5;
    __syncthreads();
    if ((threadIdx.x & 31) == 0) sred[w] = v;
    __syncthreads();
    float t = 0.f;
    int nw = blockDim.x >> 5;
    for (int i = 0; i < nw; i++) t += sred[i];
    return t;
}

__device__ __forceinline__ float silu_f(float x) {
    return x / (1.f + __expf(-x));
}

__device__ __forceinline__ uint32_t cvta_s(const void* p) {
    return (uint32_t)__cvta_generic_to_shared(p);
}

__device__ __forceinline__ void cpa16(uint32_t s, const void* g) {
    asm volatile("cp.async.cg.shared.global [%0], [%1], 16;" :: "r"(s), "l"(g));
}
__device__ __forceinline__ void cpa_commit() {
    asm volatile("cp.async.commit_group;");
}
template <int N_>
__device__ __forceinline__ void cpa_wait() {
    asm volatile("cp.async.wait_group %0;" :: "n"(N_));
}

__device__ __forceinline__ void ldsm4(uint32_t& r0, uint32_t& r1, uint32_t& r2, uint32_t& r3,
                                      uint32_t addr) {
    asm volatile("ldmatrix.sync.aligned.m8n8.x4.shared.b16 {%0,%1,%2,%3}, [%4];"
                 : "=r"(r0), "=r"(r1), "=r"(r2), "=r"(r3) : "r"(addr));
}

__device__ __forceinline__ void mma16816(float* d, const uint32_t* a, const uint32_t* b) {
    asm volatile("mma.sync.aligned.m16n8k16.row.col.f32.f16.f16.f32 "
                 "{%0,%1,%2,%3},{%4,%5,%6,%7},{%8,%9},{%0,%1,%2,%3};"
                 : "+f"(d[0]), "+f"(d[1]), "+f"(d[2]), "+f"(d[3])
                 : "r"(a[0]), "r"(a[1]), "r"(a[2]), "r"(a[3]), "r"(b[0]), "r"(b[1]));
}

// ----------------------------------------------------------------------------
// Weight quantization (deterministic 2-phase mean|W|)
// ----------------------------------------------------------------------------
__global__ void abssum_kernel(const float* __restrict__ W, int n, float* __restrict__ part) {
    __shared__ float sred[8];
    float s = 0.f;
    for (int i = blockIdx.x * blockDim.x + threadIdx.x; i < n; i += gridDim.x * blockDim.x)
        s += fabsf(W[i]);
    float tot = block_reduce_sum(s, sred);
    if (threadIdx.x == 0) part[blockIdx.x] = tot;
}

__global__ void finalize_scale_kernel(const float* __restrict__ part, float* __restrict__ scale, float inv_n) {
    __shared__ float sred[8];
    float tot = block_reduce_sum(part[threadIdx.x], sred);
    if (threadIdx.x == 0) *scale = fmaxf(tot * inv_n, 1e-5f);
}

// Ternary quantize -> fp16 {-1,0,1}
__global__ void quant_f16_kernel(const float* __restrict__ W, __half* __restrict__ Wh,
                                 int n, const float* __restrict__ sp) {
    float scale = *sp;
    for (int i = blockIdx.x * blockDim.x + threadIdx.x; i < n; i += gridDim.x * blockDim.x) {
        float wn = W[i] / scale;
        wn = fminf(fmaxf(wn, -1.f), 1.f);
        Wh[i] = __float2half_rn(rintf(wn));  // exact: -1/0/1
    }
}

// ----------------------------------------------------------------------------
// Fused double RMSNorm (x -> rmsnorm(w1) -> rmsnorm(w2)) with fp16 out
// ----------------------------------------------------------------------------
__global__ void rmsnorm2_f16_kernel(const float* __restrict__ in,
                                    const float* __restrict__ w1,
                                    const float* __restrict__ w2,
                                    __half* __restrict__ out) {
    __shared__ float sred[8];
    const int D = 768;
    size_t base = (size_t)blockIdx.x * D;
    float v[3], t[3];
    float ss = 0.f;
    #pragma unroll
    for (int i = 0; i < 3; i++) {
        float x = in[base + threadIdx.x + (i << 8)];
        v[i] = x;
        ss = fmaf(x, x, ss);
    }
    float tot = block_reduce_sum(ss, sred);
    float r1 = rsqrtf(tot / (float)D + 1e-6f);
    float ss2 = 0.f;
    #pragma unroll
    for (int i = 0; i < 3; i++) {
        int c = threadIdx.x + (i << 8);
        t[i] = v[i] * r1 * w1[c];
        ss2 = fmaf(t[i], t[i], ss2);
    }
    float tot2 = block_reduce_sum(ss2, sred);
    float r2 = rsqrtf(tot2 / (float)D + 1e-6f);
    #pragma unroll
    for (int i = 0; i < 3; i++) {
        int c = threadIdx.x + (i << 8);
        out[base + c] = __float2half_rn(t[i] * r2 * w2[c]);
    }
}

// Single RMSNorm with fp16 output (for y, D = 1536)
template <int CNT>
__global__ void rmsnorm_f16_kernel(const float* __restrict__ in, const float* __restrict__ w,
                                   __half* __restrict__ out) {
    __shared__ float sred[8];
    const int D = CNT * 256;
    size_t base = (size_t)blockIdx.x * D;
    float v[CNT];
    float ss = 0.f;
    #pragma unroll
    for (int i = 0; i < CNT; i++) {
        float x = in[base + threadIdx.x + (i << 8)];
        v[i] = x;
        ss = fmaf(x, x, ss);
    }
    float tot = block_reduce_sum(ss, sred);
    float r = rsqrtf(tot / (float)D + 1e-6f);
    #pragma unroll
    for (int i = 0; i < CNT; i++) {
        int c = threadIdx.x + (i << 8);
        out[base + c] = __float2half_rn(v[i] * r * w[c]);
    }
}

// ----------------------------------------------------------------------------
// fp16 tensor-core GEMM: C[M,N] = (A[M,K] * B[N,K]^T) * scale (+Res)
// BM=128, BN=128, BK=32, 3-stage cp.async pipeline, one sync per k-tile.
// ----------------------------------------------------------------------------
#define LDS_   40
#define TILEE  (128 * LDS_)     // fp16 elems per stage per matrix
#define GSTG   3
#define GEMM_SMEM (GSTG * TILEE * 2 * 2)  // bytes

__global__ __launch_bounds__(256)
void gemm_f16_kernel(const __half* __restrict__ A,
                     const __half* __restrict__ B,
                     float* __restrict__ C, const float* __restrict__ Res,
                     const float* __restrict__ scalep,
                     int M, int N, int K2) {
    extern __shared__ __half smem_[];
    __half* sA = smem_;
    __half* sB = smem_ + GSTG * TILEE;

    int tid  = threadIdx.x;
    int lane = tid & 31;
    int warp = tid >> 5;
    int wm = warp >> 1;
    int wn = warp & 1;
    int bm = blockIdx.y * 128;
    int bn = blockIdx.x * 128;

    int r0 = tid >> 2;
    int c0 = (tid & 3) << 3;
    const __half* Ag0 = A + (size_t)(bm + r0) * K2 + c0;
    const __half* Ag1 = A + (size_t)(bm + r0 + 64) * K2 + c0;
    const __half* Bg0 = B + (size_t)(bn + r0) * K2 + c0;
    const __half* Bg1 = B + (size_t)(bn + r0 + 64) * K2 + c0;

    uint32_t sAbase = cvta_s(sA);
    uint32_t sBbase = cvta_s(sB);
    uint32_t st0 = (uint32_t)((r0 * LDS_ + c0) * 2);
    uint32_t st1 = st0 + (uint32_t)(64 * LDS_ * 2);

    int aRow = wm * 32 + (lane & 15);
    int aCol = (lane >> 4) << 3;
    uint32_t aFrag = (uint32_t)((aRow * LDS_ + aCol) * 2);
    int bRow = wn * 64 + (((lane >> 4) & 1) << 3) + (lane & 7);
    int bCol = ((lane >> 3) & 1) << 3;
    uint32_t bFrag = (uint32_t)((bRow * LDS_ + bCol) * 2);

    float acc[2][8][4];
    #pragma unroll
    for (int i = 0; i < 2; i++)
        #pragma unroll
        for (int j = 0; j < 8; j++)
            #pragma unroll
            for (int k = 0; k < 4; k++) acc[i][j][k] = 0.f;

    int KT = K2 >> 5;

    // prologue: issue tiles 0 and 1 into stages 0 and 1
    #pragma unroll
    for (int t = 0; t < 2; t++) {
        size_t ko = (size_t)t << 5;
        uint32_t ao = sAbase + (uint32_t)(t * TILEE * 2);
        uint32_t bo = sBbase + (uint32_t)(t * TILEE * 2);
        cpa16(ao + st0, Ag0 + ko); cpa16(ao + st1, Ag1 + ko);
        cpa16(bo + st0, Bg0 + ko); cpa16(bo + st1, Bg1 + ko);
        cpa_commit();
    }

    int s = 0;
    for (int kt = 0; kt < KT; kt++) {
        if (kt == KT - 1) cpa_wait<0>(); else cpa_wait<1>();
        __syncthreads();
        if (kt + 2 < KT) {
            int sn = s + 2; if (sn >= GSTG) sn -= GSTG;
            size_t ko = (size_t)(kt + 2) << 5;
            uint32_t ao = sAbase + (uint32_t)(sn * TILEE * 2);
            uint32_t bo = sBbase + (uint32_t)(sn * TILEE * 2);
            cpa16(ao + st0, Ag0 + ko); cpa16(ao + st1, Ag1 + ko);
            cpa16(bo + st0, Bg0 + ko); cpa16(bo + st1, Bg1 + ko);
            cpa_commit();
        }

        uint32_t aS = sAbase + (uint32_t)(s * TILEE * 2) + aFrag;
        uint32_t bS = sBbase + (uint32_t)(s * TILEE * 2) + bFrag;
        #pragma unroll
        for (int ks = 0; ks < 2; ks++) {
            uint32_t kb = (uint32_t)(ks * 16 * 2);
            uint32_t a[2][4];
            ldsm4(a[0][0], a[0][1], a[0][2], a[0][3], aS + kb);
            ldsm4(a[1][0], a[1][1], a[1][2], a[1][3], aS + (16 * LDS_ * 2) + kb);
            uint32_t bf[8][2];
            #pragma unroll
            for (int p = 0; p < 4; p++) {
                ldsm4(bf[2 * p][0], bf[2 * p][1], bf[2 * p + 1][0], bf[2 * p + 1][1],
                      bS + (uint32_t)(p * 16 * LDS_ * 2) + kb);
            }
            #pragma unroll
            for (int mt = 0; mt < 2; mt++)
                #pragma unroll
                for (int nt = 0; nt < 8; nt++)
                    mma16816(acc[mt][nt], a[mt], bf[nt]);
        }
        s++; if (s >= GSTG) s = 0;
    }

    float sc = __ldg(scalep);
    int er = bm + wm * 32 + (lane >> 2);
    int ec = bn + wn * 64 + ((lane & 3) << 1);
    #pragma unroll
    for (int mt = 0; mt < 2; mt++) {
        #pragma unroll
        for (int h = 0; h < 2; h++) {
            int row = er + mt * 16 + h * 8;
            #pragma unroll
            for (int nt = 0; nt < 8; nt++) {
                size_t off = (size_t)row * N + ec + nt * 8;
                float2 o;
                o.x = acc[mt][nt][2 * h + 0] * sc;
                o.y = acc[mt][nt][2 * h + 1] * sc;
                if (Res) {
                    o.x += Res[off];
                    o.y += Res[off + 1];
                }
                *(float2*)(C + off) = o;
            }
        }
    }
}

// ----------------------------------------------------------------------------
// Causal depthwise conv (K=4) + bias + SiLU — 4 tokens per thread
// ----------------------------------------------------------------------------
__global__ void conv_silu_kernel(const float* __restrict__ cw, const float* __restrict__ cb) {
    int idx = blockIdx.x * blockDim.x + threadIdx.x;
    const int TOT = (BL / 4) * DIN;
    if (idx >= TOT) return;
    int d = idx % DIN;
    int q = idx / DIN;
    int m0 = q << 2;
    int l0 = m0 & (LL - 1);
    float w0 = cw[d * 4], w1 = cw[d * 4 + 1], w2 = cw[d * 4 + 2], w3 = cw[d * 4 + 3];
    float bias = cb[d];
    float xw[7];
    #pragma unroll
    for (int i = 0; i < 7; i++) {
        int l = l0 + i - 3;
        xw[i] = (l >= 0) ? g_xz[(size_t)(m0 + i - 3) * (2 * DIN) + d] : 0.f;
    }
    #pragma unroll
    for (int t = 0; t < 4; t++) {
        float acc = bias;
        acc = fmaf(xw[t],     w0, acc);
        acc = fmaf(xw[t + 1], w1, acc);
        acc = fmaf(xw[t + 2], w2, acc);
        acc = fmaf(xw[t + 3], w3, acc);
        g_xc[(size_t)(m0 + t) * DIN + d] = silu_f(acc);
    }
}

// ----------------------------------------------------------------------------
// dbc = xc @ W_x^T  — tiled GEMM (BM=64 tokens, all 33 outputs, BK=64)
// ----------------------------------------------------------------------------
__global__ __launch_bounds__(256)
void dbc_kernel(const float* __restrict__ Wx) {
    __shared__ float sA[64][65];
    __shared__ float sB[33][65];
    int tid = threadIdx.x;
    int m0 = blockIdx.x * 64;
    int row = tid >> 2;
    int og  = tid & 3;
    float acc[9];
    #pragma unroll
    for (int j = 0; j < 9; j++) acc[j] = 0.f;

    for (int k0 = 0; k0 < DIN; k0 += 64) {
        #pragma unroll
        for (int i = tid; i < 64 * 16; i += 256) {
            int r = i >> 4;
            int c4 = (i & 15) << 2;
            float4 v = *(const float4*)(g_xc + (size_t)(m0 + r) * DIN + k0 + c4);
            sA[r][c4] = v.x; sA[r][c4 + 1] = v.y; sA[r][c4 + 2] = v.z; sA[r][c4 + 3] = v.w;
        }
        for (int i = tid; i < 33 * 16; i += 256) {
            int r = i >> 4;
            int c4 = (i & 15) << 2;
            float4 v = *(const float4*)(Wx + (size_t)r * DIN + k0 + c4);
            sB[r][c4] = v.x; sB[r][c4 + 1] = v.y; sB[r][c4 + 2] = v.z; sB[r][c4 + 3] = v.w;
        }
        __syncthreads();
        #pragma unroll 8
        for (int kk = 0; kk < 64; kk++) {
            float a = sA[row][kk];
            #pragma unroll
            for (int j = 0; j < 9; j++) {
                int o = og + 4 * j;
                if (o < 33) acc[j] = fmaf(a, sB[o][kk], acc[j]);
            }
        }
        __syncthreads();
    }
    #pragma unroll
    for (int j = 0; j < 9; j++) {
        int o = og + 4 * j;
        if (o < 33) g_dbc[(size_t)(m0 + row) * 33 + o] = acc[j];
    }
}

// ----------------------------------------------------------------------------
// Chunked selective scan
// ----------------------------------------------------------------------------
__global__ void scan_phase1(const float* __restrict__ dt_w, const float* __restrict__ dt_b,
                            const float* __restrict__ A_log) {
    int blk = blockIdx.x;
    int dblk = blk % (DIN / 32);
    int tmp = blk / (DIN / 32);
    int c = tmp % CH;
    int b = tmp / CH;
    int ng = threadIdx.x & 3;
    int dloc = threadIdx.x >> 2;
    int d = dblk * 32 + dloc;

    float A4[4], h[4];
    #pragma unroll
    for (int j = 0; j < 4; j++) {
        A4[j] = -expf(A_log[d * NN + ng * 4 + j]);
        h[j] = 0.f;
    }
    float dtw = dt_w[d], dtb = dt_b[d];
    float sumdelta = 0.f;
    size_t mbase = (size_t)b * LL + (size_t)c * CLEN;

    for (int l = 0; l < CLEN; l++) {
        size_t m = mbase + l;
        const float* dbc = g_dbc + m * 33;
        float dt = __ldg(dbc);
        float sp_in = fmaf(dt, dtw, dtb);
        float delta = (sp_in > 20.f) ? sp_in : log1pf(__expf(sp_in));
        sumdelta += delta;
        float u  = g_xc[m * DIN + d];
        float du = delta * u;
        #pragma unroll
        for (int j = 0; j < 4; j++) {
            float dA = __expf(delta * A4[j]);
            h[j] = fmaf(dA, h[j], du * __ldg(dbc + 1 + ng * 4 + j));
        }
    }
    size_t base = (((size_t)(b * CH + c)) * DIN + d) * NN + ng * 4;
    float4 st; st.x = h[0]; st.y = h[1]; st.z = h[2]; st.w = h[3];
    *(float4*)(g_carry + base) = st;
    if (ng == 0) g_sumd[(b * CH + c) * DIN + d] = sumdelta;
}

__global__ void scan_phase2(const float* __restrict__ A_log) {
    int idx = blockIdx.x * blockDim.x + threadIdx.x;
    if (idx >= BB * DIN * NN) return;
    int n = idx % NN;
    int d = (idx / NN) % DIN;
    int b = idx / (NN * DIN);
    float A = -expf(A_log[d * NN + n]);
    float h = 0.f;
    #pragma unroll
    for (int c = 0; c < CH; c++) {
        size_t o = (((size_t)(b * CH + c)) * DIN + d) * NN + n;
        float loc = g_carry[o];
        g_carry[o] = h;
        float P = __expf(A * g_sumd[(b * CH + c) * DIN + d]);
        h = fmaf(P, h, loc);
    }
}

__global__ void scan_phase3(const float* __restrict__ dt_w, const float* __restrict__ dt_b,
                            const float* __restrict__ A_log, const float* __restrict__ D_param) {
    int blk = blockIdx.x;
    int dblk = blk % (DIN / 32);
    int tmp = blk / (DIN / 32);
    int c = tmp % CH;
    int b = tmp / CH;
    int ng = threadIdx.x & 3;
    int dloc = threadIdx.x >> 2;
    int d = dblk * 32 + dloc;

    float A4[4], h[4];
    size_t cbase = (((size_t)(b * CH + c)) * DIN + d) * NN + ng * 4;
    float4 h0 = *(const float4*)(g_carry + cbase);
    h[0] = h0.x; h[1] = h0.y; h[2] = h0.z; h[3] = h0.w;
    #pragma unroll
    for (int j = 0; j < 4; j++)
        A4[j] = -expf(A_log[d * NN + ng * 4 + j]);

    float dtw = dt_w[d], dtb = dt_b[d], Dp = D_param[d];
    size_t mbase = (size_t)b * LL + (size_t)c * CLEN;

    for (int l = 0; l < CLEN; l++) {
        size_t m = mbase + l;
        const float* dbc = g_dbc + m * 33;
        float dt = __ldg(dbc);
        float sp_in = fmaf(dt, dtw, dtb);
        float delta = (sp_in > 20.f) ? sp_in : log1pf(__expf(sp_in));
        float u  = g_xc[m * DIN + d];
        float du = delta * u;
        float y = 0.f;
        #pragma unroll
        for (int j = 0; j < 4; j++) {
            int n = ng * 4 + j;
            float dA = __expf(delta * A4[j]);
            h[j] = fmaf(dA, h[j], du * __ldg(dbc + 1 + n));
            y = fmaf(h[j], __ldg(dbc + 17 + n), y);
        }
        y += __shfl_xor_sync(0xffffffffu, y, 1);
        y += __shfl_xor_sync(0xffffffffu, y, 2);
        if (ng == 0) {
            float yy = fmaf(u, Dp, y);
            float z = g_xz[m * (2 * DIN) + DIN + d];
            g_y[m * DIN + d] = yy * silu_f(z);
        }
    }
}

// ----------------------------------------------------------------------------
// Launch
// ----------------------------------------------------------------------------
extern "C" void kernel_launch(void* const* d_in, const int* in_sizes, int n_in,
                              void* d_out, int out_size) {
    const float* x         = (const float*)d_in[0];
    const float* norm_w    = (const float*)d_in[1];
    const float* in_norm_w = (const float*)d_in[2];
    const float* W_in      = (const float*)d_in[3];
    const float* conv_w    = (const float*)d_in[4];
    const float* conv_b    = (const float*)d_in[5];
    const float* W_x       = (const float*)d_in[6];
    const float* dt_w      = (const float*)d_in[7];
    const float* dt_b      = (const float*)d_in[8];
    const float* A_log     = (const float*)d_in[9];
    const float* D_param   = (const float*)d_in[10];
    const float* out_norm_w = (const float*)d_in[11];
    const float* W_out      = (const float*)d_in[12];
    float* out = (float*)d_out;

    float *p_xz, *p_y, *p_part, *p_scale;
    __half *p_A1, *p_A2, *p_B1, *p_B2;
    cudaGetSymbolAddress((void**)&p_xz,    g_xz);
    cudaGetSymbolAddress((void**)&p_y,     g_y);
    cudaGetSymbolAddress((void**)&p_part,  g_part);
    cudaGetSymbolAddress((void**)&p_scale, g_scale);
    cudaGetSymbolAddress((void**)&p_A1,    g_A1);
    cudaGetSymbolAddress((void**)&p_A2,    g_A2);
    cudaGetSymbolAddress((void**)&p_B1,    g_B1);
    cudaGetSymbolAddress((void**)&p_B2,    g_B2);

    cudaFuncSetAttribute(gemm_f16_kernel, cudaFuncAttributeMaxDynamicSharedMemorySize, GEMM_SMEM);

    const int nWin  = 2 * DIN * DM;   // 2359296
    const int nWout = DM * DIN;       // 1179648

    // 1) Weight scales
    abssum_kernel<<<256, 256>>>(W_in,  nWin,  p_part);
    abssum_kernel<<<256, 256>>>(W_out, nWout, p_part + 256);
    finalize_scale_kernel<<<1, 256>>>(p_part,       p_scale,     1.f / (float)nWin);
    finalize_scale_kernel<<<1, 256>>>(p_part + 256, p_scale + 1, 1.f / (float)nWout);

    // 2) Ternary-quantize weights to fp16; scale applied in GEMM epilogue
    quant_f16_kernel<<<1024, 256>>>(W_in,  p_B1, nWin,  p_scale);
    quant_f16_kernel<<<1024, 256>>>(W_out, p_B2, nWout, p_scale + 1);

    // 3) Fused double RMSNorm x -> fp16 A1
    rmsnorm2_f16_kernel<<<BL, 256>>>(x, norm_w, in_norm_w, p_A1);

    // 4) xz = (A1 @ B1^T) * scale0   [8192 x 3072], K=768
    {
        dim3 grid(2 * DIN / 128, BL / 128);
        gemm_f16_kernel<<<grid, 256, GEMM_SMEM>>>(p_A1, p_B1, p_xz, nullptr, p_scale, BL, 2 * DIN, DM);
    }

    // 5) Causal conv + SiLU (4 tokens/thread)
    conv_silu_kernel<<<((BL / 4) * DIN + 255) / 256, 256>>>(conv_w, conv_b);

    // 6) dbc = xc @ W_x^T (tiled)
    dbc_kernel<<<BL / 64, 256>>>(W_x);

    // 7) Chunked selective scan
    scan_phase1<<<BB * CH * (DIN / 32), 128>>>(dt_w, dt_b, A_log);
    scan_phase2<<<(BB * DIN * NN + 255) / 256, 256>>>(A_log);
    scan_phase3<<<BB * CH * (DIN / 32), 128>>>(dt_w, dt_b, A_log, D_param);

    // 8) RMSNorm y -> fp16 A2
    rmsnorm_f16_kernel<6><<<BL, 256>>>(p_y, out_norm_w, p_A2);

    // 9) out = (A2 @ B2^T) * scale1 + residual(x)   [8192 x 768], K=1536
    {
        dim3 grid(DM / 128, BL / 128);
        gemm_f16_kernel<<<grid, 256, GEMM_SMEM>>>(p_A2, p_B2, out, x, p_scale + 1, BL, DM, DIN);
    }
}

// round 6
// speedup vs baseline: 4.3110x; 1.0249x over previous
#include <cuda_runtime.h>
#include <cuda_fp16.h>
#include <math.h>
#include <stdint.h>

// Problem dims (fixed for this instance)
#define BB   4
#define LL   2048
#define DM   768
#define DIN  1536
#define NN   16
#define KK   4
#define BL   (BB*LL)          // 8192 tokens
#define CH   16               // scan chunks
#define CLEN (LL/CH)          // 128

// ----------------------------------------------------------------------------
// Device scratch
// ----------------------------------------------------------------------------
__device__ float g_xz [BL*2*DIN];                // bitlinear output [x_path | z]
__device__ float g_xc [BL*DIN];                  // conv + silu
__device__ float g_dbc[BL*33];                   // [dt | B(16) | C(16)]
__device__ float g_y  [BL*DIN];                  // scan output * silu(z)
__device__ __half g_A1[BL*DM];                   // fp16 rmsnorm2(x) [M, DM]
__device__ __half g_A2[BL*DIN];                  // fp16 rmsnorm(y)  [M, DIN]
__device__ __half g_B1[2*DIN*DM];                // ternary W_in  fp16 [3072, 768]
__device__ __half g_B2[DM*DIN];                  // ternary W_out fp16 [768, 1536]
__device__ float g_carry[BB*CH*DIN*NN];          // chunk carries / h_in (in-place)
__device__ float g_sumd [BB*CH*DIN];             // per-chunk sum of delta
__device__ float g_part[512];                    // reduction partials
__device__ float g_scale[2];                     // scales for W_in / W_out

// ----------------------------------------------------------------------------
// Helpers
// ----------------------------------------------------------------------------
__device__ __forceinline__ float block_reduce_sum(float v, float* sred) {
    #pragma unroll
    for (int s = 16; s; s >>= 1) v += __shfl_xor_sync(0xffffffffu, v, s);
    int w = threadIdx.x >> 5;
    __syncthreads();
    if ((threadIdx.x & 31) == 0) sred[w] = v;
    __syncthreads();
    float t = 0.f;
    int nw = blockDim.x >> 5;
    for (int i = 0; i < nw; i++) t += sred[i];
    return t;
}

__device__ __forceinline__ float silu_f(float x) {
    return x / (1.f + __expf(-x));
}

__device__ __forceinline__ uint32_t cvta_s(const void* p) {
    return (uint32_t)__cvta_generic_to_shared(p);
}

__device__ __forceinline__ void cpa16(uint32_t s, const void* g) {
    asm volatile("cp.async.cg.shared.global [%0], [%1], 16;" :: "r"(s), "l"(g));
}
__device__ __forceinline__ void cpa_commit() {
    asm volatile("cp.async.commit_group;");
}
template <int N_>
__device__ __forceinline__ void cpa_wait() {
    asm volatile("cp.async.wait_group %0;" :: "n"(N_));
}

__device__ __forceinline__ void ldsm4(uint32_t& r0, uint32_t& r1, uint32_t& r2, uint32_t& r3,
                                      uint32_t addr) {
    asm volatile("ldmatrix.sync.aligned.m8n8.x4.shared.b16 {%0,%1,%2,%3}, [%4];"
                 : "=r"(r0), "=r"(r1), "=r"(r2), "=r"(r3) : "r"(addr));
}

__device__ __forceinline__ void mma16816(float* d, const uint32_t* a, const uint32_t* b) {
    asm volatile("mma.sync.aligned.m16n8k16.row.col.f32.f16.f16.f32 "
                 "{%0,%1,%2,%3},{%4,%5,%6,%7},{%8,%9},{%0,%1,%2,%3};"
                 : "+f"(d[0]), "+f"(d[1]), "+f"(d[2]), "+f"(d[3])
                 : "r"(a[0]), "r"(a[1]), "r"(a[2]), "r"(a[3]), "r"(b[0]), "r"(b[1]));
}

// ----------------------------------------------------------------------------
// Weight quantization (deterministic 2-phase mean|W|)
// ----------------------------------------------------------------------------
__global__ void abssum_kernel(const float* __restrict__ W, int n, float* __restrict__ part) {
    __shared__ float sred[8];
    float s = 0.f;
    for (int i = blockIdx.x * blockDim.x + threadIdx.x; i < n; i += gridDim.x * blockDim.x)
        s += fabsf(W[i]);
    float tot = block_reduce_sum(s, sred);
    if (threadIdx.x == 0) part[blockIdx.x] = tot;
}

__global__ void finalize_scale_kernel(const float* __restrict__ part, float* __restrict__ scale, float inv_n) {
    __shared__ float sred[8];
    float tot = block_reduce_sum(part[threadIdx.x], sred);
    if (threadIdx.x == 0) *scale = fmaxf(tot * inv_n, 1e-5f);
}

// Ternary quantize -> fp16 {-1,0,1}
__global__ void quant_f16_kernel(const float* __restrict__ W, __half* __restrict__ Wh,
                                 int n, const float* __restrict__ sp) {
    float scale = *sp;
    for (int i = blockIdx.x * blockDim.x + threadIdx.x; i < n; i += gridDim.x * blockDim.x) {
        float wn = W[i] / scale;
        wn = fminf(fmaxf(wn, -1.f), 1.f);
        Wh[i] = __float2half_rn(rintf(wn));  // exact: -1/0/1
    }
}

// ----------------------------------------------------------------------------
// Fused double RMSNorm (x -> rmsnorm(w1) -> rmsnorm(w2)) with fp16 out
// ----------------------------------------------------------------------------
__global__ void rmsnorm2_f16_kernel(const float* __restrict__ in,
                                    const float* __restrict__ w1,
                                    const float* __restrict__ w2,
                                    __half* __restrict__ out) {
    __shared__ float sred[8];
    const int D = 768;
    size_t base = (size_t)blockIdx.x * D;
    float v[3], t[3];
    float ss = 0.f;
    #pragma unroll
    for (int i = 0; i < 3; i++) {
        float x = in[base + threadIdx.x + (i << 8)];
        v[i] = x;
        ss = fmaf(x, x, ss);
    }
    float tot = block_reduce_sum(ss, sred);
    float r1 = rsqrtf(tot / (float)D + 1e-6f);
    float ss2 = 0.f;
    #pragma unroll
    for (int i = 0; i < 3; i++) {
        int c = threadIdx.x + (i << 8);
        t[i] = v[i] * r1 * w1[c];
        ss2 = fmaf(t[i], t[i], ss2);
    }
    float tot2 = block_reduce_sum(ss2, sred);
    float r2 = rsqrtf(tot2 / (float)D + 1e-6f);
    #pragma unroll
    for (int i = 0; i < 3; i++) {
        int c = threadIdx.x + (i << 8);
        out[base + c] = __float2half_rn(t[i] * r2 * w2[c]);
    }
}

// Single RMSNorm with fp16 output (for y, D = 1536)
template <int CNT>
__global__ void rmsnorm_f16_kernel(const float* __restrict__ in, const float* __restrict__ w,
                                   __half* __restrict__ out) {
    __shared__ float sred[8];
    const int D = CNT * 256;
    size_t base = (size_t)blockIdx.x * D;
    float v[CNT];
    float ss = 0.f;
    #pragma unroll
    for (int i = 0; i < CNT; i++) {
        float x = in[base + threadIdx.x + (i << 8)];
        v[i] = x;
        ss = fmaf(x, x, ss);
    }
    float tot = block_reduce_sum(ss, sred);
    float r = rsqrtf(tot / (float)D + 1e-6f);
    #pragma unroll
    for (int i = 0; i < CNT; i++) {
        int c = threadIdx.x + (i << 8);
        out[base + c] = __float2half_rn(v[i] * r * w[c]);
    }
}

// ----------------------------------------------------------------------------
// fp16 tensor-core GEMM: C[M,N] = (A[M,K] * B[N,K]^T) * scale (+Res)
// BM=128, BN=128, BK=32, 3-stage cp.async pipeline; 2 CTAs/SM to hide stalls.
// ----------------------------------------------------------------------------
#define LDS_   40
#define TILEE  (128 * LDS_)     // fp16 elems per stage per matrix
#define GSTG   3
#define GEMM_SMEM (GSTG * TILEE * 2 * 2)  // bytes (61440)

__global__ __launch_bounds__(256, 2)
void gemm_f16_kernel(const __half* __restrict__ A,
                     const __half* __restrict__ B,
                     float* __restrict__ C, const float* __restrict__ Res,
                     const float* __restrict__ scalep,
                     int M, int N, int K2) {
    extern __shared__ __half smem_[];
    __half* sA = smem_;
    __half* sB = smem_ + GSTG * TILEE;

    int tid  = threadIdx.x;
    int lane = tid & 31;
    int warp = tid >> 5;
    int wm = warp >> 1;
    int wn = warp & 1;
    int bm = blockIdx.y * 128;
    int bn = blockIdx.x * 128;

    int r0 = tid >> 2;
    int c0 = (tid & 3) << 3;
    const __half* Ag0 = A + (size_t)(bm + r0) * K2 + c0;
    const __half* Ag1 = A + (size_t)(bm + r0 + 64) * K2 + c0;
    const __half* Bg0 = B + (size_t)(bn + r0) * K2 + c0;
    const __half* Bg1 = B + (size_t)(bn + r0 + 64) * K2 + c0;

    uint32_t sAbase = cvta_s(sA);
    uint32_t sBbase = cvta_s(sB);
    uint32_t st0 = (uint32_t)((r0 * LDS_ + c0) * 2);
    uint32_t st1 = st0 + (uint32_t)(64 * LDS_ * 2);

    int aRow = wm * 32 + (lane & 15);
    int aCol = (lane >> 4) << 3;
    uint32_t aFrag = (uint32_t)((aRow * LDS_ + aCol) * 2);
    int bRow = wn * 64 + (((lane >> 4) & 1) << 3) + (lane & 7);
    int bCol = ((lane >> 3) & 1) << 3;
    uint32_t bFrag = (uint32_t)((bRow * LDS_ + bCol) * 2);

    float acc[2][8][4];
    #pragma unroll
    for (int i = 0; i < 2; i++)
        #pragma unroll
        for (int j = 0; j < 8; j++)
            #pragma unroll
            for (int k = 0; k < 4; k++) acc[i][j][k] = 0.f;

    int KT = K2 >> 5;

    // prologue: issue tiles 0 and 1 into stages 0 and 1
    #pragma unroll
    for (int t = 0; t < 2; t++) {
        size_t ko = (size_t)t << 5;
        uint32_t ao = sAbase + (uint32_t)(t * TILEE * 2);
        uint32_t bo = sBbase + (uint32_t)(t * TILEE * 2);
        cpa16(ao + st0, Ag0 + ko); cpa16(ao + st1, Ag1 + ko);
        cpa16(bo + st0, Bg0 + ko); cpa16(bo + st1, Bg1 + ko);
        cpa_commit();
    }

    int s = 0;
    for (int kt = 0; kt < KT; kt++) {
        if (kt == KT - 1) cpa_wait<0>(); else cpa_wait<1>();
        __syncthreads();
        if (kt + 2 < KT) {
            int sn = s + 2; if (sn >= GSTG) sn -= GSTG;
            size_t ko = (size_t)(kt + 2) << 5;
            uint32_t ao = sAbase + (uint32_t)(sn * TILEE * 2);
            uint32_t bo = sBbase + (uint32_t)(sn * TILEE * 2);
            cpa16(ao + st0, Ag0 + ko); cpa16(ao + st1, Ag1 + ko);
            cpa16(bo + st0, Bg0 + ko); cpa16(bo + st1, Bg1 + ko);
            cpa_commit();
        }

        uint32_t aS = sAbase + (uint32_t)(s * TILEE * 2) + aFrag;
        uint32_t bS = sBbase + (uint32_t)(s * TILEE * 2) + bFrag;
        #pragma unroll
        for (int ks = 0; ks < 2; ks++) {
            uint32_t kb = (uint32_t)(ks * 16 * 2);
            uint32_t a[2][4];
            ldsm4(a[0][0], a[0][1], a[0][2], a[0][3], aS + kb);
            ldsm4(a[1][0], a[1][1], a[1][2], a[1][3], aS + (16 * LDS_ * 2) + kb);
            uint32_t bf[8][2];
            #pragma unroll
            for (int p = 0; p < 4; p++) {
                ldsm4(bf[2 * p][0], bf[2 * p][1], bf[2 * p + 1][0], bf[2 * p + 1][1],
                      bS + (uint32_t)(p * 16 * LDS_ * 2) + kb);
            }
            #pragma unroll
            for (int mt = 0; mt < 2; mt++)
                #pragma unroll
                for (int nt = 0; nt < 8; nt++)
                    mma16816(acc[mt][nt], a[mt], bf[nt]);
        }
        s++; if (s >= GSTG) s = 0;
    }

    float sc = __ldg(scalep);
    int er = bm + wm * 32 + (lane >> 2);
    int ec = bn + wn * 64 + ((lane & 3) << 1);
    #pragma unroll
    for (int mt = 0; mt < 2; mt++) {
        #pragma unroll
        for (int h = 0; h < 2; h++) {
            int row = er + mt * 16 + h * 8;
            #pragma unroll
            for (int nt = 0; nt < 8; nt++) {
                size_t off = (size_t)row * N + ec + nt * 8;
                float2 o;
                o.x = acc[mt][nt][2 * h + 0] * sc;
                o.y = acc[mt][nt][2 * h + 1] * sc;
                if (Res) {
                    o.x += Res[off];
                    o.y += Res[off + 1];
                }
                *(float2*)(C + off) = o;
            }
        }
    }
}

// ----------------------------------------------------------------------------
// Causal depthwise conv (K=4) + bias + SiLU — 4 tokens per thread
// ----------------------------------------------------------------------------
__global__ void conv_silu_kernel(const float* __restrict__ cw, const float* __restrict__ cb) {
    int idx = blockIdx.x * blockDim.x + threadIdx.x;
    const int TOT = (BL / 4) * DIN;
    if (idx >= TOT) return;
    int d = idx % DIN;
    int q = idx / DIN;
    int m0 = q << 2;
    int l0 = m0 & (LL - 1);
    float w0 = cw[d * 4], w1 = cw[d * 4 + 1], w2 = cw[d * 4 + 2], w3 = cw[d * 4 + 3];
    float bias = cb[d];
    float xw[7];
    #pragma unroll
    for (int i = 0; i < 7; i++) {
        int l = l0 + i - 3;
        xw[i] = (l >= 0) ? g_xz[(size_t)(m0 + i - 3) * (2 * DIN) + d] : 0.f;
    }
    #pragma unroll
    for (int t = 0; t < 4; t++) {
        float acc = bias;
        acc = fmaf(xw[t],     w0, acc);
        acc = fmaf(xw[t + 1], w1, acc);
        acc = fmaf(xw[t + 2], w2, acc);
        acc = fmaf(xw[t + 3], w3, acc);
        g_xc[(size_t)(m0 + t) * DIN + d] = silu_f(acc);
    }
}

// ----------------------------------------------------------------------------
// dbc = xc @ W_x^T  — tiled GEMM (BM=64 tokens, all 33 outputs, BK=64)
// ----------------------------------------------------------------------------
__global__ __launch_bounds__(256)
void dbc_kernel(const float* __restrict__ Wx) {
    __shared__ float sA[64][65];
    __shared__ float sB[33][65];
    int tid = threadIdx.x;
    int m0 = blockIdx.x * 64;
    int row = tid >> 2;
    int og  = tid & 3;
    float acc[9];
    #pragma unroll
    for (int j = 0; j < 9; j++) acc[j] = 0.f;

    for (int k0 = 0; k0 < DIN; k0 += 64) {
        #pragma unroll
        for (int i = tid; i < 64 * 16; i += 256) {
            int r = i >> 4;
            int c4 = (i & 15) << 2;
            float4 v = *(const float4*)(g_xc + (size_t)(m0 + r) * DIN + k0 + c4);
            sA[r][c4] = v.x; sA[r][c4 + 1] = v.y; sA[r][c4 + 2] = v.z; sA[r][c4 + 3] = v.w;
        }
        for (int i = tid; i < 33 * 16; i += 256) {
            int r = i >> 4;
            int c4 = (i & 15) << 2;
            float4 v = *(const float4*)(Wx + (size_t)r * DIN + k0 + c4);
            sB[r][c4] = v.x; sB[r][c4 + 1] = v.y; sB[r][c4 + 2] = v.z; sB[r][c4 + 3] = v.w;
        }
        __syncthreads();
        #pragma unroll 8
        for (int kk = 0; kk < 64; kk++) {
            float a = sA[row][kk];
            #pragma unroll
            for (int j = 0; j < 9; j++) {
                int o = og + 4 * j;
                if (o < 33) acc[j] = fmaf(a, sB[o][kk], acc[j]);
            }
        }
        __syncthreads();
    }
    #pragma unroll
    for (int j = 0; j < 9; j++) {
        int o = og + 4 * j;
        if (o < 33) g_dbc[(size_t)(m0 + row) * 33 + o] = acc[j];
    }
}

// ----------------------------------------------------------------------------
// Chunked selective scan (CH=16, CLEN=128)
// ----------------------------------------------------------------------------
__global__ void scan_phase1(const float* __restrict__ dt_w, const float* __restrict__ dt_b,
                            const float* __restrict__ A_log) {
    int blk = blockIdx.x;
    int dblk = blk % (DIN / 32);
    int tmp = blk / (DIN / 32);
    int c = tmp % CH;
    int b = tmp / CH;
    int ng = threadIdx.x & 3;
    int dloc = threadIdx.x >> 2;
    int d = dblk * 32 + dloc;

    float A4[4], h[4];
    #pragma unroll
    for (int j = 0; j < 4; j++) {
        A4[j] = -expf(A_log[d * NN + ng * 4 + j]);
        h[j] = 0.f;
    }
    float dtw = dt_w[d], dtb = dt_b[d];
    float sumdelta = 0.f;
    size_t mbase = (size_t)b * LL + (size_t)c * CLEN;

    for (int l = 0; l < CLEN; l++) {
        size_t m = mbase + l;
        const float* dbc = g_dbc + m * 33;
        float dt = __ldg(dbc);
        float sp_in = fmaf(dt, dtw, dtb);
        float delta = (sp_in > 20.f) ? sp_in : log1pf(__expf(sp_in));
        sumdelta += delta;
        float u  = g_xc[m * DIN + d];
        float du = delta * u;
        #pragma unroll
        for (int j = 0; j < 4; j++) {
            float dA = __expf(delta * A4[j]);
            h[j] = fmaf(dA, h[j], du * __ldg(dbc + 1 + ng * 4 + j));
        }
    }
    size_t base = (((size_t)(b * CH + c)) * DIN + d) * NN + ng * 4;
    float4 st; st.x = h[0]; st.y = h[1]; st.z = h[2]; st.w = h[3];
    *(float4*)(g_carry + base) = st;
    if (ng == 0) g_sumd[(b * CH + c) * DIN + d] = sumdelta;
}

__global__ void scan_phase2(const float* __restrict__ A_log) {
    int idx = blockIdx.x * blockDim.x + threadIdx.x;
    if (idx >= BB * DIN * NN) return;
    int n = idx % NN;
    int d = (idx / NN) % DIN;
    int b = idx / (NN * DIN);
    float A = -expf(A_log[d * NN + n]);
    float h = 0.f;
    #pragma unroll
    for (int c = 0; c < CH; c++) {
        size_t o = (((size_t)(b * CH + c)) * DIN + d) * NN + n;
        float loc = g_carry[o];
        g_carry[o] = h;
        float P = __expf(A * g_sumd[(b * CH + c) * DIN + d]);
        h = fmaf(P, h, loc);
    }
}

__global__ void scan_phase3(const float* __restrict__ dt_w, const float* __restrict__ dt_b,
                            const float* __restrict__ A_log, const float* __restrict__ D_param) {
    int blk = blockIdx.x;
    int dblk = blk % (DIN / 32);
    int tmp = blk / (DIN / 32);
    int c = tmp % CH;
    int b = tmp / CH;
    int ng = threadIdx.x & 3;
    int dloc = threadIdx.x >> 2;
    int d = dblk * 32 + dloc;

    float A4[4], h[4];
    size_t cbase = (((size_t)(b * CH + c)) * DIN + d) * NN + ng * 4;
    float4 h0 = *(const float4*)(g_carry + cbase);
    h[0] = h0.x; h[1] = h0.y; h[2] = h0.z; h[3] = h0.w;
    #pragma unroll
    for (int j = 0; j < 4; j++)
        A4[j] = -expf(A_log[d * NN + ng * 4 + j]);

    float dtw = dt_w[d], dtb = dt_b[d], Dp = D_param[d];
    size_t mbase = (size_t)b * LL + (size_t)c * CLEN;

    for (int l = 0; l < CLEN; l++) {
        size_t m = mbase + l;
        const float* dbc = g_dbc + m * 33;
        float dt = __ldg(dbc);
        float sp_in = fmaf(dt, dtw, dtb);
        float delta = (sp_in > 20.f) ? sp_in : log1pf(__expf(sp_in));
        float u  = g_xc[m * DIN + d];
        float du = delta * u;
        float y = 0.f;
        #pragma unroll
        for (int j = 0; j < 4; j++) {
            int n = ng * 4 + j;
            float dA = __expf(delta * A4[j]);
            h[j] = fmaf(dA, h[j], du * __ldg(dbc + 1 + n));
            y = fmaf(h[j], __ldg(dbc + 17 + n), y);
        }
        y += __shfl_xor_sync(0xffffffffu, y, 1);
        y += __shfl_xor_sync(0xffffffffu, y, 2);
        if (ng == 0) {
            float yy = fmaf(u, Dp, y);
            float z = g_xz[m * (2 * DIN) + DIN + d];
            g_y[m * DIN + d] = yy * silu_f(z);
        }
    }
}

// ----------------------------------------------------------------------------
// Launch
// ----------------------------------------------------------------------------
extern "C" void kernel_launch(void* const* d_in, const int* in_sizes, int n_in,
                              void* d_out, int out_size) {
    const float* x         = (const float*)d_in[0];
    const float* norm_w    = (const float*)d_in[1];
    const float* in_norm_w = (const float*)d_in[2];
    const float* W_in      = (const float*)d_in[3];
    const float* conv_w    = (const float*)d_in[4];
    const float* conv_b    = (const float*)d_in[5];
    const float* W_x       = (const float*)d_in[6];
    const float* dt_w      = (const float*)d_in[7];
    const float* dt_b      = (const float*)d_in[8];
    const float* A_log     = (const float*)d_in[9];
    const float* D_param   = (const float*)d_in[10];
    const float* out_norm_w = (const float*)d_in[11];
    const float* W_out      = (const float*)d_in[12];
    float* out = (float*)d_out;

    float *p_xz, *p_y, *p_part, *p_scale;
    __half *p_A1, *p_A2, *p_B1, *p_B2;
    cudaGetSymbolAddress((void**)&p_xz,    g_xz);
    cudaGetSymbolAddress((void**)&p_y,     g_y);
    cudaGetSymbolAddress((void**)&p_part,  g_part);
    cudaGetSymbolAddress((void**)&p_scale, g_scale);
    cudaGetSymbolAddress((void**)&p_A1,    g_A1);
    cudaGetSymbolAddress((void**)&p_A2,    g_A2);
    cudaGetSymbolAddress((void**)&p_B1,    g_B1);
    cudaGetSymbolAddress((void**)&p_B2,    g_B2);

    cudaFuncSetAttribute(gemm_f16_kernel, cudaFuncAttributeMaxDynamicSharedMemorySize, GEMM_SMEM);

    const int nWin  = 2 * DIN * DM;   // 2359296
    const int nWout = DM * DIN;       // 1179648

    // 1) Weight scales
    abssum_kernel<<<256, 256>>>(W_in,  nWin,  p_part);
    abssum_kernel<<<256, 256>>>(W_out, nWout, p_part + 256);
    finalize_scale_kernel<<<1, 256>>>(p_part,       p_scale,     1.f / (float)nWin);
    finalize_scale_kernel<<<1, 256>>>(p_part + 256, p_scale + 1, 1.f / (float)nWout);

    // 2) Ternary-quantize weights to fp16; scale applied in GEMM epilogue
    quant_f16_kernel<<<1024, 256>>>(W_in,  p_B1, nWin,  p_scale);
    quant_f16_kernel<<<1024, 256>>>(W_out, p_B2, nWout, p_scale + 1);

    // 3) Fused double RMSNorm x -> fp16 A1
    rmsnorm2_f16_kernel<<<BL, 256>>>(x, norm_w, in_norm_w, p_A1);

    // 4) xz = (A1 @ B1^T) * scale0   [8192 x 3072], K=768
    {
        dim3 grid(2 * DIN / 128, BL / 128);
        gemm_f16_kernel<<<grid, 256, GEMM_SMEM>>>(p_A1, p_B1, p_xz, nullptr, p_scale, BL, 2 * DIN, DM);
    }

    // 5) Causal conv + SiLU (4 tokens/thread)
    conv_silu_kernel<<<((BL / 4) * DIN + 255) / 256, 256>>>(conv_w, conv_b);

    // 6) dbc = xc @ W_x^T (tiled)
    dbc_kernel<<<BL / 64, 256>>>(W_x);

    // 7) Chunked selective scan (CH=16)
    scan_phase1<<<BB * CH * (DIN / 32), 128>>>(dt_w, dt_b, A_log);
    scan_phase2<<<(BB * DIN * NN + 255) / 256, 256>>>(A_log);
    scan_phase3<<<BB * CH * (DIN / 32), 128>>>(dt_w, dt_b, A_log, D_param);

    // 8) RMSNorm y -> fp16 A2
    rmsnorm_f16_kernel<6><<<BL, 256>>>(p_y, out_norm_w, p_A2);

    // 9) out = (A2 @ B2^T) * scale1 + residual(x)   [8192 x 768], K=1536
    {
        dim3 grid(DM / 128, BL / 128);
        gemm_f16_kernel<<<grid, 256, GEMM_SMEM>>>(p_A2, p_B2, out, x, p_scale + 1, BL, DM, DIN);
    }
}

// round 7
// speedup vs baseline: 4.5913x; 1.0650x over previous
#include <cuda_runtime.h>
#include <cuda_fp16.h>
#include <math.h>
#include <stdint.h>

// Problem dims (fixed for this instance)
#define BB   4
#define LL   2048
#define DM   768
#define DIN  1536
#define NN   16
#define KK   4
#define BL   (BB*LL)          // 8192 tokens
#define CH   16               // scan chunks
#define CLEN (LL/CH)          // 128

// ----------------------------------------------------------------------------
// Device scratch
// ----------------------------------------------------------------------------
__device__ __half g_xz [BL*2*DIN];               // bitlinear output [x_path | z] (fp16)
__device__ __half g_xc [BL*DIN];                 // conv + silu (fp16)
__device__ float  g_dbc[BL*33];                  // [dt | B(16) | C(16)]
__device__ __half g_y  [BL*DIN];                 // scan output * silu(z) (fp16)
__device__ __half g_A1[BL*DM];                   // fp16 rmsnorm2(x) [M, DM]
__device__ __half g_A2[BL*DIN];                  // fp16 rmsnorm(y)  [M, DIN]
__device__ __half g_B1[2*DIN*DM];                // ternary W_in  fp16 [3072, 768]
__device__ __half g_B2[DM*DIN];                  // ternary W_out fp16 [768, 1536]
__device__ float g_carry[BB*CH*DIN*NN];          // chunk carries / h_in (in-place)
__device__ float g_sumd [BB*CH*DIN];             // per-chunk sum of delta
__device__ float g_part[512];                    // reduction partials
__device__ float g_scale[2];                     // scales for W_in / W_out

// ----------------------------------------------------------------------------
// Helpers
// ----------------------------------------------------------------------------
__device__ __forceinline__ float block_reduce_sum(float v, float* sred) {
    #pragma unroll
    for (int s = 16; s; s >>= 1) v += __shfl_xor_sync(0xffffffffu, v, s);
    int w = threadIdx.x >> 5;
    __syncthreads();
    if ((threadIdx.x & 31) == 0) sred[w] = v;
    __syncthreads();
    float t = 0.f;
    int nw = blockDim.x >> 5;
    for (int i = 0; i < nw; i++) t += sred[i];
    return t;
}

__device__ __forceinline__ float silu_f(float x) {
    return x / (1.f + __expf(-x));
}

__device__ __forceinline__ uint32_t cvta_s(const void* p) {
    return (uint32_t)__cvta_generic_to_shared(p);
}

__device__ __forceinline__ void cpa16(uint32_t s, const void* g) {
    asm volatile("cp.async.cg.shared.global [%0], [%1], 16;" :: "r"(s), "l"(g));
}
__device__ __forceinline__ void cpa_commit() {
    asm volatile("cp.async.commit_group;");
}
template <int N_>
__device__ __forceinline__ void cpa_wait() {
    asm volatile("cp.async.wait_group %0;" :: "n"(N_));
}

__device__ __forceinline__ void ldsm4(uint32_t& r0, uint32_t& r1, uint32_t& r2, uint32_t& r3,
                                      uint32_t addr) {
    asm volatile("ldmatrix.sync.aligned.m8n8.x4.shared.b16 {%0,%1,%2,%3}, [%4];"
                 : "=r"(r0), "=r"(r1), "=r"(r2), "=r"(r3) : "r"(addr));
}

__device__ __forceinline__ void mma16816(float* d, const uint32_t* a, const uint32_t* b) {
    asm volatile("mma.sync.aligned.m16n8k16.row.col.f32.f16.f16.f32 "
                 "{%0,%1,%2,%3},{%4,%5,%6,%7},{%8,%9},{%0,%1,%2,%3};"
                 : "+f"(d[0]), "+f"(d[1]), "+f"(d[2]), "+f"(d[3])
                 : "r"(a[0]), "r"(a[1]), "r"(a[2]), "r"(a[3]), "r"(b[0]), "r"(b[1]));
}

// ----------------------------------------------------------------------------
// Weight quantization (deterministic 2-phase mean|W|)
// ----------------------------------------------------------------------------
__global__ void abssum_kernel(const float* __restrict__ W, int n, float* __restrict__ part) {
    __shared__ float sred[8];
    float s = 0.f;
    for (int i = blockIdx.x * blockDim.x + threadIdx.x; i < n; i += gridDim.x * blockDim.x)
        s += fabsf(W[i]);
    float tot = block_reduce_sum(s, sred);
    if (threadIdx.x == 0) part[blockIdx.x] = tot;
}

__global__ void finalize_scale_kernel(const float* __restrict__ part, float* __restrict__ scale, float inv_n) {
    __shared__ float sred[8];
    float tot = block_reduce_sum(part[threadIdx.x], sred);
    if (threadIdx.x == 0) *scale = fmaxf(tot * inv_n, 1e-5f);
}

// Ternary quantize -> fp16 {-1,0,1}
__global__ void quant_f16_kernel(const float* __restrict__ W, __half* __restrict__ Wh,
                                 int n, const float* __restrict__ sp) {
    float scale = *sp;
    for (int i = blockIdx.x * blockDim.x + threadIdx.x; i < n; i += gridDim.x * blockDim.x) {
        float wn = W[i] / scale;
        wn = fminf(fmaxf(wn, -1.f), 1.f);
        Wh[i] = __float2half_rn(rintf(wn));  // exact: -1/0/1
    }
}

// ----------------------------------------------------------------------------
// Fused double RMSNorm (x -> rmsnorm(w1) -> rmsnorm(w2)) with fp16 out
// ----------------------------------------------------------------------------
__global__ void rmsnorm2_f16_kernel(const float* __restrict__ in,
                                    const float* __restrict__ w1,
                                    const float* __restrict__ w2,
                                    __half* __restrict__ out) {
    __shared__ float sred[8];
    const int D = 768;
    size_t base = (size_t)blockIdx.x * D;
    float v[3], t[3];
    float ss = 0.f;
    #pragma unroll
    for (int i = 0; i < 3; i++) {
        float x = in[base + threadIdx.x + (i << 8)];
        v[i] = x;
        ss = fmaf(x, x, ss);
    }
    float tot = block_reduce_sum(ss, sred);
    float r1 = rsqrtf(tot / (float)D + 1e-6f);
    float ss2 = 0.f;
    #pragma unroll
    for (int i = 0; i < 3; i++) {
        int c = threadIdx.x + (i << 8);
        t[i] = v[i] * r1 * w1[c];
        ss2 = fmaf(t[i], t[i], ss2);
    }
    float tot2 = block_reduce_sum(ss2, sred);
    float r2 = rsqrtf(tot2 / (float)D + 1e-6f);
    #pragma unroll
    for (int i = 0; i < 3; i++) {
        int c = threadIdx.x + (i << 8);
        out[base + c] = __float2half_rn(t[i] * r2 * w2[c]);
    }
}

// RMSNorm with fp16 input and fp16 output (for y, D = 1536)
template <int CNT>
__global__ void rmsnorm_h2h_kernel(const __half* __restrict__ in, const float* __restrict__ w,
                                   __half* __restrict__ out) {
    __shared__ float sred[8];
    const int D = CNT * 256;
    size_t base = (size_t)blockIdx.x * D;
    float v[CNT];
    float ss = 0.f;
    #pragma unroll
    for (int i = 0; i < CNT; i++) {
        float x = __half2float(in[base + threadIdx.x + (i << 8)]);
        v[i] = x;
        ss = fmaf(x, x, ss);
    }
    float tot = block_reduce_sum(ss, sred);
    float r = rsqrtf(tot / (float)D + 1e-6f);
    #pragma unroll
    for (int i = 0; i < CNT; i++) {
        int c = threadIdx.x + (i << 8);
        out[base + c] = __float2half_rn(v[i] * r * w[c]);
    }
}

// ----------------------------------------------------------------------------
// fp16 tensor-core GEMM: C[M,N] = (A[M,K] * B[N,K]^T) * scale (+Res)
// BM=128, BN=128, BK=32, 3-stage cp.async pipeline; 2 CTAs/SM.
// HALF_OUT: write __half C (no residual). else: float C (+Res).
// ----------------------------------------------------------------------------
#define LDS_   40
#define TILEE  (128 * LDS_)     // fp16 elems per stage per matrix
#define GSTG   3
#define GEMM_SMEM (GSTG * TILEE * 2 * 2)  // bytes (61440)

template <bool HALF_OUT>
__global__ __launch_bounds__(256, 2)
void gemm_f16_kernel(const __half* __restrict__ A,
                     const __half* __restrict__ B,
                     void* __restrict__ Cv, const float* __restrict__ Res,
                     const float* __restrict__ scalep,
                     int M, int N, int K2) {
    extern __shared__ __half smem_[];
    __half* sA = smem_;
    __half* sB = smem_ + GSTG * TILEE;

    int tid  = threadIdx.x;
    int lane = tid & 31;
    int warp = tid >> 5;
    int wm = warp >> 1;
    int wn = warp & 1;
    int bm = blockIdx.y * 128;
    int bn = blockIdx.x * 128;

    int r0 = tid >> 2;
    int c0 = (tid & 3) << 3;
    const __half* Ag0 = A + (size_t)(bm + r0) * K2 + c0;
    const __half* Ag1 = A + (size_t)(bm + r0 + 64) * K2 + c0;
    const __half* Bg0 = B + (size_t)(bn + r0) * K2 + c0;
    const __half* Bg1 = B + (size_t)(bn + r0 + 64) * K2 + c0;

    uint32_t sAbase = cvta_s(sA);
    uint32_t sBbase = cvta_s(sB);
    uint32_t st0 = (uint32_t)((r0 * LDS_ + c0) * 2);
    uint32_t st1 = st0 + (uint32_t)(64 * LDS_ * 2);

    int aRow = wm * 32 + (lane & 15);
    int aCol = (lane >> 4) << 3;
    uint32_t aFrag = (uint32_t)((aRow * LDS_ + aCol) * 2);
    int bRow = wn * 64 + (((lane >> 4) & 1) << 3) + (lane & 7);
    int bCol = ((lane >> 3) & 1) << 3;
    uint32_t bFrag = (uint32_t)((bRow * LDS_ + bCol) * 2);

    float acc[2][8][4];
    #pragma unroll
    for (int i = 0; i < 2; i++)
        #pragma unroll
        for (int j = 0; j < 8; j++)
            #pragma unroll
            for (int k = 0; k < 4; k++) acc[i][j][k] = 0.f;

    int KT = K2 >> 5;

    // prologue: issue tiles 0 and 1 into stages 0 and 1
    #pragma unroll
    for (int t = 0; t < 2; t++) {
        size_t ko = (size_t)t << 5;
        uint32_t ao = sAbase + (uint32_t)(t * TILEE * 2);
        uint32_t bo = sBbase + (uint32_t)(t * TILEE * 2);
        cpa16(ao + st0, Ag0 + ko); cpa16(ao + st1, Ag1 + ko);
        cpa16(bo + st0, Bg0 + ko); cpa16(bo + st1, Bg1 + ko);
        cpa_commit();
    }

    int s = 0;
    for (int kt = 0; kt < KT; kt++) {
        if (kt == KT - 1) cpa_wait<0>(); else cpa_wait<1>();
        __syncthreads();
        if (kt + 2 < KT) {
            int sn = s + 2; if (sn >= GSTG) sn -= GSTG;
            size_t ko = (size_t)(kt + 2) << 5;
            uint32_t ao = sAbase + (uint32_t)(sn * TILEE * 2);
            uint32_t bo = sBbase + (uint32_t)(sn * TILEE * 2);
            cpa16(ao + st0, Ag0 + ko); cpa16(ao + st1, Ag1 + ko);
            cpa16(bo + st0, Bg0 + ko); cpa16(bo + st1, Bg1 + ko);
            cpa_commit();
        }

        uint32_t aS = sAbase + (uint32_t)(s * TILEE * 2) + aFrag;
        uint32_t bS = sBbase + (uint32_t)(s * TILEE * 2) + bFrag;
        #pragma unroll
        for (int ks = 0; ks < 2; ks++) {
            uint32_t kb = (uint32_t)(ks * 16 * 2);
            uint32_t a[2][4];
            ldsm4(a[0][0], a[0][1], a[0][2], a[0][3], aS + kb);
            ldsm4(a[1][0], a[1][1], a[1][2], a[1][3], aS + (16 * LDS_ * 2) + kb);
            uint32_t bf[8][2];
            #pragma unroll
            for (int p = 0; p < 4; p++) {
                ldsm4(bf[2 * p][0], bf[2 * p][1], bf[2 * p + 1][0], bf[2 * p + 1][1],
                      bS + (uint32_t)(p * 16 * LDS_ * 2) + kb);
            }
            #pragma unroll
            for (int mt = 0; mt < 2; mt++)
                #pragma unroll
                for (int nt = 0; nt < 8; nt++)
                    mma16816(acc[mt][nt], a[mt], bf[nt]);
        }
        s++; if (s >= GSTG) s = 0;
    }

    float sc = __ldg(scalep);
    int er = bm + wm * 32 + (lane >> 2);
    int ec = bn + wn * 64 + ((lane & 3) << 1);
    #pragma unroll
    for (int mt = 0; mt < 2; mt++) {
        #pragma unroll
        for (int h = 0; h < 2; h++) {
            int row = er + mt * 16 + h * 8;
            #pragma unroll
            for (int nt = 0; nt < 8; nt++) {
                size_t off = (size_t)row * N + ec + nt * 8;
                float ox = acc[mt][nt][2 * h + 0] * sc;
                float oy = acc[mt][nt][2 * h + 1] * sc;
                if (HALF_OUT) {
                    *(__half2*)((__half*)Cv + off) = __floats2half2_rn(ox, oy);
                } else {
                    float2 o;
                    o.x = ox + Res[off];
                    o.y = oy + Res[off + 1];
                    *(float2*)((float*)Cv + off) = o;
                }
            }
        }
    }
}

// ----------------------------------------------------------------------------
// Causal depthwise conv (K=4) + bias + SiLU — 4 tokens per thread (fp16 io)
// ----------------------------------------------------------------------------
__global__ void conv_silu_kernel(const float* __restrict__ cw, const float* __restrict__ cb) {
    int idx = blockIdx.x * blockDim.x + threadIdx.x;
    const int TOT = (BL / 4) * DIN;
    if (idx >= TOT) return;
    int d = idx % DIN;
    int q = idx / DIN;
    int m0 = q << 2;
    int l0 = m0 & (LL - 1);
    float w0 = cw[d * 4], w1 = cw[d * 4 + 1], w2 = cw[d * 4 + 2], w3 = cw[d * 4 + 3];
    float bias = cb[d];
    float xw[7];
    #pragma unroll
    for (int i = 0; i < 7; i++) {
        int l = l0 + i - 3;
        xw[i] = (l >= 0) ? __half2float(g_xz[(size_t)(m0 + i - 3) * (2 * DIN) + d]) : 0.f;
    }
    #pragma unroll
    for (int t = 0; t < 4; t++) {
        float acc = bias;
        acc = fmaf(xw[t],     w0, acc);
        acc = fmaf(xw[t + 1], w1, acc);
        acc = fmaf(xw[t + 2], w2, acc);
        acc = fmaf(xw[t + 3], w3, acc);
        g_xc[(size_t)(m0 + t) * DIN + d] = __float2half_rn(silu_f(acc));
    }
}

// ----------------------------------------------------------------------------
// dbc = xc @ W_x^T  — tiled GEMM (BM=64 tokens, all 33 outputs, BK=64)
// ----------------------------------------------------------------------------
__global__ __launch_bounds__(256)
void dbc_kernel(const float* __restrict__ Wx) {
    __shared__ float sA[64][65];
    __shared__ float sB[33][65];
    int tid = threadIdx.x;
    int m0 = blockIdx.x * 64;
    int row = tid >> 2;
    int og  = tid & 3;
    float acc[9];
    #pragma unroll
    for (int j = 0; j < 9; j++) acc[j] = 0.f;

    for (int k0 = 0; k0 < DIN; k0 += 64) {
        #pragma unroll
        for (int i = tid; i < 64 * 16; i += 256) {
            int r = i >> 4;
            int c4 = (i & 15) << 2;
            // 4 halves = 8 bytes
            uint2 raw = *(const uint2*)(g_xc + (size_t)(m0 + r) * DIN + k0 + c4);
            __half2 h01 = *(__half2*)&raw.x;
            __half2 h23 = *(__half2*)&raw.y;
            float2 f01 = __half22float2(h01);
            float2 f23 = __half22float2(h23);
            sA[r][c4] = f01.x; sA[r][c4 + 1] = f01.y; sA[r][c4 + 2] = f23.x; sA[r][c4 + 3] = f23.y;
        }
        for (int i = tid; i < 33 * 16; i += 256) {
            int r = i >> 4;
            int c4 = (i & 15) << 2;
            float4 v = *(const float4*)(Wx + (size_t)r * DIN + k0 + c4);
            sB[r][c4] = v.x; sB[r][c4 + 1] = v.y; sB[r][c4 + 2] = v.z; sB[r][c4 + 3] = v.w;
        }
        __syncthreads();
        #pragma unroll 8
        for (int kk = 0; kk < 64; kk++) {
            float a = sA[row][kk];
            #pragma unroll
            for (int j = 0; j < 9; j++) {
                int o = og + 4 * j;
                if (o < 33) acc[j] = fmaf(a, sB[o][kk], acc[j]);
            }
        }
        __syncthreads();
    }
    #pragma unroll
    for (int j = 0; j < 9; j++) {
        int o = og + 4 * j;
        if (o < 33) g_dbc[(size_t)(m0 + row) * 33 + o] = acc[j];
    }
}

// ----------------------------------------------------------------------------
// Chunked selective scan (CH=16, CLEN=128)
// ----------------------------------------------------------------------------
__global__ void scan_phase1(const float* __restrict__ dt_w, const float* __restrict__ dt_b,
                            const float* __restrict__ A_log) {
    int blk = blockIdx.x;
    int dblk = blk % (DIN / 32);
    int tmp = blk / (DIN / 32);
    int c = tmp % CH;
    int b = tmp / CH;
    int ng = threadIdx.x & 3;
    int dloc = threadIdx.x >> 2;
    int d = dblk * 32 + dloc;

    float A4[4], h[4];
    #pragma unroll
    for (int j = 0; j < 4; j++) {
        A4[j] = -expf(A_log[d * NN + ng * 4 + j]);
        h[j] = 0.f;
    }
    float dtw = dt_w[d], dtb = dt_b[d];
    float sumdelta = 0.f;
    size_t mbase = (size_t)b * LL + (size_t)c * CLEN;

    for (int l = 0; l < CLEN; l++) {
        size_t m = mbase + l;
        const float* dbc = g_dbc + m * 33;
        float dt = __ldg(dbc);
        float sp_in = fmaf(dt, dtw, dtb);
        float delta = (sp_in > 20.f) ? sp_in : log1pf(__expf(sp_in));
        sumdelta += delta;
        float u  = __half2float(g_xc[m * DIN + d]);
        float du = delta * u;
        #pragma unroll
        for (int j = 0; j < 4; j++) {
            float dA = __expf(delta * A4[j]);
            h[j] = fmaf(dA, h[j], du * __ldg(dbc + 1 + ng * 4 + j));
        }
    }
    size_t base = (((size_t)(b * CH + c)) * DIN + d) * NN + ng * 4;
    float4 st; st.x = h[0]; st.y = h[1]; st.z = h[2]; st.w = h[3];
    *(float4*)(g_carry + base) = st;
    if (ng == 0) g_sumd[(b * CH + c) * DIN + d] = sumdelta;
}

__global__ void scan_phase2(const float* __restrict__ A_log) {
    int idx = blockIdx.x * blockDim.x + threadIdx.x;
    if (idx >= BB * DIN * NN) return;
    int n = idx % NN;
    int d = (idx / NN) % DIN;
    int b = idx / (NN * DIN);
    float A = -expf(A_log[d * NN + n]);
    float h = 0.f;
    #pragma unroll
    for (int c = 0; c < CH; c++) {
        size_t o = (((size_t)(b * CH + c)) * DIN + d) * NN + n;
        float loc = g_carry[o];
        g_carry[o] = h;
        float P = __expf(A * g_sumd[(b * CH + c) * DIN + d]);
        h = fmaf(P, h, loc);
    }
}

__global__ void scan_phase3(const float* __restrict__ dt_w, const float* __restrict__ dt_b,
                            const float* __restrict__ A_log, const float* __restrict__ D_param) {
    int blk = blockIdx.x;
    int dblk = blk % (DIN / 32);
    int tmp = blk / (DIN / 32);
    int c = tmp % CH;
    int b = tmp / CH;
    int ng = threadIdx.x & 3;
    int dloc = threadIdx.x >> 2;
    int d = dblk * 32 + dloc;

    float A4[4], h[4];
    size_t cbase = (((size_t)(b * CH + c)) * DIN + d) * NN + ng * 4;
    float4 h0 = *(const float4*)(g_carry + cbase);
    h[0] = h0.x; h[1] = h0.y; h[2] = h0.z; h[3] = h0.w;
    #pragma unroll
    for (int j = 0; j < 4; j++)
        A4[j] = -expf(A_log[d * NN + ng * 4 + j]);

    float dtw = dt_w[d], dtb = dt_b[d], Dp = D_param[d];
    size_t mbase = (size_t)b * LL + (size_t)c * CLEN;

    for (int l = 0; l < CLEN; l++) {
        size_t m = mbase + l;
        const float* dbc = g_dbc + m * 33;
        float dt = __ldg(dbc);
        float sp_in = fmaf(dt, dtw, dtb);
        float delta = (sp_in > 20.f) ? sp_in : log1pf(__expf(sp_in));
        float u  = __half2float(g_xc[m * DIN + d]);
        float du = delta * u;
        float y = 0.f;
        #pragma unroll
        for (int j = 0; j < 4; j++) {
            int n = ng * 4 + j;
            float dA = __expf(delta * A4[j]);
            h[j] = fmaf(dA, h[j], du * __ldg(dbc + 1 + n));
            y = fmaf(h[j], __ldg(dbc + 17 + n), y);
        }
        y += __shfl_xor_sync(0xffffffffu, y, 1);
        y += __shfl_xor_sync(0xffffffffu, y, 2);
        if (ng == 0) {
            float yy = fmaf(u, Dp, y);
            float z = __half2float(g_xz[m * (2 * DIN) + DIN + d]);
            g_y[m * DIN + d] = __float2half_rn(yy * silu_f(z));
        }
    }
}

// ----------------------------------------------------------------------------
// Launch
// ----------------------------------------------------------------------------
extern "C" void kernel_launch(void* const* d_in, const int* in_sizes, int n_in,
                              void* d_out, int out_size) {
    const float* x         = (const float*)d_in[0];
    const float* norm_w    = (const float*)d_in[1];
    const float* in_norm_w = (const float*)d_in[2];
    const float* W_in      = (const float*)d_in[3];
    const float* conv_w    = (const float*)d_in[4];
    const float* conv_b    = (const float*)d_in[5];
    const float* W_x       = (const float*)d_in[6];
    const float* dt_w      = (const float*)d_in[7];
    const float* dt_b      = (const float*)d_in[8];
    const float* A_log     = (const float*)d_in[9];
    const float* D_param   = (const float*)d_in[10];
    const float* out_norm_w = (const float*)d_in[11];
    const float* W_out      = (const float*)d_in[12];
    float* out = (float*)d_out;

    float *p_part, *p_scale;
    __half *p_xz, *p_y, *p_A1, *p_A2, *p_B1, *p_B2;
    cudaGetSymbolAddress((void**)&p_xz,    g_xz);
    cudaGetSymbolAddress((void**)&p_y,     g_y);
    cudaGetSymbolAddress((void**)&p_part,  g_part);
    cudaGetSymbolAddress((void**)&p_scale, g_scale);
    cudaGetSymbolAddress((void**)&p_A1,    g_A1);
    cudaGetSymbolAddress((void**)&p_A2,    g_A2);
    cudaGetSymbolAddress((void**)&p_B1,    g_B1);
    cudaGetSymbolAddress((void**)&p_B2,    g_B2);

    cudaFuncSetAttribute(gemm_f16_kernel<true>,  cudaFuncAttributeMaxDynamicSharedMemorySize, GEMM_SMEM);
    cudaFuncSetAttribute(gemm_f16_kernel<false>, cudaFuncAttributeMaxDynamicSharedMemorySize, GEMM_SMEM);

    const int nWin  = 2 * DIN * DM;   // 2359296
    const int nWout = DM * DIN;       // 1179648

    // 1) Weight scales
    abssum_kernel<<<256, 256>>>(W_in,  nWin,  p_part);
    abssum_kernel<<<256, 256>>>(W_out, nWout, p_part + 256);
    finalize_scale_kernel<<<1, 256>>>(p_part,       p_scale,     1.f / (float)nWin);
    finalize_scale_kernel<<<1, 256>>>(p_part + 256, p_scale + 1, 1.f / (float)nWout);

    // 2) Ternary-quantize weights to fp16; scale applied in GEMM epilogue
    quant_f16_kernel<<<1024, 256>>>(W_in,  p_B1, nWin,  p_scale);
    quant_f16_kernel<<<1024, 256>>>(W_out, p_B2, nWout, p_scale + 1);

    // 3) Fused double RMSNorm x -> fp16 A1
    rmsnorm2_f16_kernel<<<BL, 256>>>(x, norm_w, in_norm_w, p_A1);

    // 4) xz = (A1 @ B1^T) * scale0   [8192 x 3072] -> fp16
    {
        dim3 grid(2 * DIN / 128, BL / 128);
        gemm_f16_kernel<true><<<grid, 256, GEMM_SMEM>>>(p_A1, p_B1, p_xz, nullptr, p_scale, BL, 2 * DIN, DM);
    }

    // 5) Causal conv + SiLU (4 tokens/thread)
    conv_silu_kernel<<<((BL / 4) * DIN + 255) / 256, 256>>>(conv_w, conv_b);

    // 6) dbc = xc @ W_x^T (tiled)
    dbc_kernel<<<BL / 64, 256>>>(W_x);

    // 7) Chunked selective scan (CH=16)
    scan_phase1<<<BB * CH * (DIN / 32), 128>>>(dt_w, dt_b, A_log);
    scan_phase2<<<(BB * DIN * NN + 255) / 256, 256>>>(A_log);
    scan_phase3<<<BB * CH * (DIN / 32), 128>>>(dt_w, dt_b, A_log, D_param);

    // 8) RMSNorm y -> fp16 A2
    rmsnorm_h2h_kernel<6><<<BL, 256>>>(p_y, out_norm_w, p_A2);

    // 9) out = (A2 @ B2^T) * scale1 + residual(x)   [8192 x 768] fp32
    {
        dim3 grid(DM / 128, BL / 128);
        gemm_f16_kernel<false><<<grid, 256, GEMM_SMEM>>>(p_A2, p_B2, out, x, p_scale + 1, BL, DM, DIN);
    }
}

// round 8
// speedup vs baseline: 5.9639x; 1.2990x over previous
#include <cuda_runtime.h>
#include <cuda_fp16.h>
#include <math.h>
#include <stdint.h>

// Problem dims (fixed for this instance)
#define BB   4
#define LL   2048
#define DM   768
#define DIN  1536
#define NN   16
#define KK   4
#define BL   (BB*LL)          // 8192 tokens
#define CH   16               // scan chunks
#define CLEN (LL/CH)          // 128

#define NWIN  (2*DIN*DM)      // 2359296
#define NWOUT (DM*DIN)        // 1179648

// ----------------------------------------------------------------------------
// Device scratch
// ----------------------------------------------------------------------------
__device__ __half g_xz [BL*2*DIN];               // bitlinear output [x_path | z] (fp16)
__device__ __half g_xc [BL*DIN];                 // conv + silu (fp16)
__device__ float  g_dbc[BL*33];                  // [dt | B(16) | C(16)]
__device__ __half g_y  [BL*DIN];                 // scan output * silu(z) (fp16)
__device__ __half g_A1[BL*DM];                   // fp16 rmsnorm2(x) [M, DM]
__device__ __half g_A2[BL*DIN];                  // fp16 rmsnorm(y)  [M, DIN]
__device__ __half g_B1[NWIN];                    // ternary W_in  fp16 [3072, 768]
__device__ __half g_B2[NWOUT];                   // ternary W_out fp16 [768, 1536]
__device__ float g_carry[BB*CH*DIN*NN];          // chunk carries / h_in (in-place)
__device__ float g_sumd [BB*CH*DIN];             // per-chunk sum of delta
__device__ float g_part[512];                    // reduction partials
__device__ float g_scale[2];                     // scales for W_in / W_out

// ----------------------------------------------------------------------------
// Helpers
// ----------------------------------------------------------------------------
__device__ __forceinline__ float block_reduce_sum(float v, float* sred) {
    #pragma unroll
    for (int s = 16; s; s >>= 1) v += __shfl_xor_sync(0xffffffffu, v, s);
    int w = threadIdx.x >> 5;
    __syncthreads();
    if ((threadIdx.x & 31) == 0) sred[w] = v;
    __syncthreads();
    float t = 0.f;
    int nw = blockDim.x >> 5;
    for (int i = 0; i < nw; i++) t += sred[i];
    return t;
}

__device__ __forceinline__ float silu_f(float x) {
    return x / (1.f + __expf(-x));
}

__device__ __forceinline__ uint32_t cvta_s(const void* p) {
    return (uint32_t)__cvta_generic_to_shared(p);
}

__device__ __forceinline__ void cpa16(uint32_t s, const void* g) {
    asm volatile("cp.async.cg.shared.global [%0], [%1], 16;" :: "r"(s), "l"(g));
}
__device__ __forceinline__ void cpa_commit() {
    asm volatile("cp.async.commit_group;");
}
template <int N_>
__device__ __forceinline__ void cpa_wait() {
    asm volatile("cp.async.wait_group %0;" :: "n"(N_));
}

__device__ __forceinline__ void ldsm4(uint32_t& r0, uint32_t& r1, uint32_t& r2, uint32_t& r3,
                                      uint32_t addr) {
    asm volatile("ldmatrix.sync.aligned.m8n8.x4.shared.b16 {%0,%1,%2,%3}, [%4];"
                 : "=r"(r0), "=r"(r1), "=r"(r2), "=r"(r3) : "r"(addr));
}

__device__ __forceinline__ void mma16816(float* d, const uint32_t* a, const uint32_t* b) {
    asm volatile("mma.sync.aligned.m16n8k16.row.col.f32.f16.f16.f32 "
                 "{%0,%1,%2,%3},{%4,%5,%6,%7},{%8,%9},{%0,%1,%2,%3};"
                 : "+f"(d[0]), "+f"(d[1]), "+f"(d[2]), "+f"(d[3])
                 : "r"(a[0]), "r"(a[1]), "r"(a[2]), "r"(a[3]), "r"(b[0]), "r"(b[1]));
}

// ----------------------------------------------------------------------------
// Weight quantization (deterministic 2-phase mean|W|) — merged kernels
// ----------------------------------------------------------------------------
__global__ void abssum2_kernel(const float* __restrict__ W1, const float* __restrict__ W2,
                               float* __restrict__ part) {
    __shared__ float sred[8];
    const float* W = (blockIdx.x < 256) ? W1 : W2;
    int n = (blockIdx.x < 256) ? NWIN : NWOUT;
    int blk = blockIdx.x & 255;
    float s = 0.f;
    for (int i = blk * blockDim.x + threadIdx.x; i < n; i += 256 * blockDim.x)
        s += fabsf(W[i]);
    float tot = block_reduce_sum(s, sred);
    if (threadIdx.x == 0) part[blockIdx.x] = tot;
}

__global__ void finalize2_kernel(const float* __restrict__ part, float* __restrict__ scale) {
    __shared__ float sred[8];
    float inv_n = (blockIdx.x == 0) ? (1.f / (float)NWIN) : (1.f / (float)NWOUT);
    float tot = block_reduce_sum(part[blockIdx.x * 256 + threadIdx.x], sred);
    if (threadIdx.x == 0) scale[blockIdx.x] = fmaxf(tot * inv_n, 1e-5f);
}

// Ternary quantize both weights -> fp16 {-1,0,1}
__global__ void quant2_kernel(const float* __restrict__ W1, const float* __restrict__ W2,
                              __half* __restrict__ B1, __half* __restrict__ B2,
                              const float* __restrict__ sp) {
    float s0 = sp[0], s1 = sp[1];
    const int total = NWIN + NWOUT;
    for (int i = blockIdx.x * blockDim.x + threadIdx.x; i < total; i += gridDim.x * blockDim.x) {
        if (i < NWIN) {
            float wn = fminf(fmaxf(W1[i] / s0, -1.f), 1.f);
            B1[i] = __float2half_rn(rintf(wn));
        } else {
            int j = i - NWIN;
            float wn = fminf(fmaxf(W2[j] / s1, -1.f), 1.f);
            B2[j] = __float2half_rn(rintf(wn));
        }
    }
}

// ----------------------------------------------------------------------------
// Fused double RMSNorm (x -> rmsnorm(w1) -> rmsnorm(w2)) with fp16 out
// ----------------------------------------------------------------------------
__global__ void rmsnorm2_f16_kernel(const float* __restrict__ in,
                                    const float* __restrict__ w1,
                                    const float* __restrict__ w2,
                                    __half* __restrict__ out) {
    __shared__ float sred[8];
    const int D = 768;
    size_t base = (size_t)blockIdx.x * D;
    float v[3], t[3];
    float ss = 0.f;
    #pragma unroll
    for (int i = 0; i < 3; i++) {
        float x = in[base + threadIdx.x + (i << 8)];
        v[i] = x;
        ss = fmaf(x, x, ss);
    }
    float tot = block_reduce_sum(ss, sred);
    float r1 = rsqrtf(tot / (float)D + 1e-6f);
    float ss2 = 0.f;
    #pragma unroll
    for (int i = 0; i < 3; i++) {
        int c = threadIdx.x + (i << 8);
        t[i] = v[i] * r1 * w1[c];
        ss2 = fmaf(t[i], t[i], ss2);
    }
    float tot2 = block_reduce_sum(ss2, sred);
    float r2 = rsqrtf(tot2 / (float)D + 1e-6f);
    #pragma unroll
    for (int i = 0; i < 3; i++) {
        int c = threadIdx.x + (i << 8);
        out[base + c] = __float2half_rn(t[i] * r2 * w2[c]);
    }
}

// RMSNorm with fp16 input and fp16 output (for y, D = 1536)
template <int CNT>
__global__ void rmsnorm_h2h_kernel(const __half* __restrict__ in, const float* __restrict__ w,
                                   __half* __restrict__ out) {
    __shared__ float sred[8];
    const int D = CNT * 256;
    size_t base = (size_t)blockIdx.x * D;
    float v[CNT];
    float ss = 0.f;
    #pragma unroll
    for (int i = 0; i < CNT; i++) {
        float x = __half2float(in[base + threadIdx.x + (i << 8)]);
        v[i] = x;
        ss = fmaf(x, x, ss);
    }
    float tot = block_reduce_sum(ss, sred);
    float r = rsqrtf(tot / (float)D + 1e-6f);
    #pragma unroll
    for (int i = 0; i < CNT; i++) {
        int c = threadIdx.x + (i << 8);
        out[base + c] = __float2half_rn(v[i] * r * w[c]);
    }
}

// ----------------------------------------------------------------------------
// fp16 tensor-core GEMM: C[M,N] = (A[M,K] * B[N,K]^T) * scale (+Res)
// BM=128, BN=128, BK=64, 3-stage cp.async pipeline, 1 sync per k-tile.
// HALF_OUT: write __half C (no residual). else: float C (+Res).
// ----------------------------------------------------------------------------
#define LDS_   72
#define TILEE  (128 * LDS_)               // fp16 elems per stage per matrix
#define GSTG   3
#define GEMM_SMEM (GSTG * TILEE * 2 * 2)  // 110592 bytes

template <bool HALF_OUT>
__global__ __launch_bounds__(256, 2)
void gemm_f16_kernel(const __half* __restrict__ A,
                     const __half* __restrict__ B,
                     void* __restrict__ Cv, const float* __restrict__ Res,
                     const float* __restrict__ scalep,
                     int M, int N, int K2) {
    extern __shared__ __half smem_[];
    __half* sA = smem_;
    __half* sB = smem_ + GSTG * TILEE;

    int tid  = threadIdx.x;
    int lane = tid & 31;
    int warp = tid >> 5;
    int wm = warp >> 1;
    int wn = warp & 1;
    int bm = blockIdx.y * 128;
    int bn = blockIdx.x * 128;

    // loader: 1024 16B-chunks per matrix per stage -> 4 per thread
    int lr = tid >> 3;               // 0..31 row group base (rows lr, lr+32, lr+64, lr+96)
    int lc = (tid & 7) << 3;         // col in halfs: 0,8,...,56
    const __half* AgBase = A + (size_t)bm * K2 + lc;
    const __half* BgBase = B + (size_t)bn * K2 + lc;

    uint32_t sAbase = cvta_s(sA);
    uint32_t sBbase = cvta_s(sB);

    int aRow = wm * 32 + (lane & 15);
    int aCol = (lane >> 4) << 3;
    uint32_t aFrag = (uint32_t)((aRow * LDS_ + aCol) * 2);
    int bRow = wn * 64 + (((lane >> 4) & 1) << 3) + (lane & 7);
    int bCol = ((lane >> 3) & 1) << 3;
    uint32_t bFrag = (uint32_t)((bRow * LDS_ + bCol) * 2);

    float acc[2][8][4];
    #pragma unroll
    for (int i = 0; i < 2; i++)
        #pragma unroll
        for (int j = 0; j < 8; j++)
            #pragma unroll
            for (int k = 0; k < 4; k++) acc[i][j][k] = 0.f;

    int KT = K2 >> 6;     // 64-wide k-tiles

    // stage loader
    auto load_stage = [&](int s, int kt) {
        uint32_t ao = sAbase + (uint32_t)(s * TILEE * 2);
        uint32_t bo = sBbase + (uint32_t)(s * TILEE * 2);
        size_t ko = (size_t)kt << 6;
        #pragma unroll
        for (int i = 0; i < 4; i++) {
            int r = lr + (i << 5);
            uint32_t so = (uint32_t)((r * LDS_ + lc) * 2);
            cpa16(ao + so, AgBase + (size_t)r * K2 + ko);
            cpa16(bo + so, BgBase + (size_t)r * K2 + ko);
        }
    };

    // prologue: stages 0, 1
    load_stage(0, 0); cpa_commit();
    if (KT > 1) { load_stage(1, 1); cpa_commit(); }

    int s = 0;
    for (int kt = 0; kt < KT; kt++) {
        if (kt + 1 < KT) cpa_wait<1>(); else cpa_wait<0>();
        __syncthreads();
        if (kt + 2 < KT) {
            int sn = s + 2; if (sn >= GSTG) sn -= GSTG;
            load_stage(sn, kt + 2);
            cpa_commit();
        }

        uint32_t aS = sAbase + (uint32_t)(s * TILEE * 2) + aFrag;
        uint32_t bS = sBbase + (uint32_t)(s * TILEE * 2) + bFrag;
        #pragma unroll
        for (int ks = 0; ks < 4; ks++) {
            uint32_t kb = (uint32_t)(ks * 16 * 2);
            uint32_t a[2][4];
            ldsm4(a[0][0], a[0][1], a[0][2], a[0][3], aS + kb);
            ldsm4(a[1][0], a[1][1], a[1][2], a[1][3], aS + (16 * LDS_ * 2) + kb);
            uint32_t bf[8][2];
            #pragma unroll
            for (int p = 0; p < 4; p++) {
                ldsm4(bf[2 * p][0], bf[2 * p][1], bf[2 * p + 1][0], bf[2 * p + 1][1],
                      bS + (uint32_t)(p * 16 * LDS_ * 2) + kb);
            }
            #pragma unroll
            for (int mt = 0; mt < 2; mt++)
                #pragma unroll
                for (int nt = 0; nt < 8; nt++)
                    mma16816(acc[mt][nt], a[mt], bf[nt]);
        }
        s++; if (s >= GSTG) s = 0;
    }

    float sc = __ldg(scalep);
    int er = bm + wm * 32 + (lane >> 2);
    int ec = bn + wn * 64 + ((lane & 3) << 1);
    #pragma unroll
    for (int mt = 0; mt < 2; mt++) {
        #pragma unroll
        for (int h = 0; h < 2; h++) {
            int row = er + mt * 16 + h * 8;
            #pragma unroll
            for (int nt = 0; nt < 8; nt++) {
                size_t off = (size_t)row * N + ec + nt * 8;
                float ox = acc[mt][nt][2 * h + 0] * sc;
                float oy = acc[mt][nt][2 * h + 1] * sc;
                if (HALF_OUT) {
                    *(__half2*)((__half*)Cv + off) = __floats2half2_rn(ox, oy);
                } else {
                    float2 o;
                    o.x = ox + Res[off];
                    o.y = oy + Res[off + 1];
                    *(float2*)((float*)Cv + off) = o;
                }
            }
        }
    }
}

// ----------------------------------------------------------------------------
// Causal depthwise conv (K=4) + bias + SiLU — 4 tokens per thread (fp16 io)
// ----------------------------------------------------------------------------
__global__ void conv_silu_kernel(const float* __restrict__ cw, const float* __restrict__ cb) {
    int idx = blockIdx.x * blockDim.x + threadIdx.x;
    const int TOT = (BL / 4) * DIN;
    if (idx >= TOT) return;
    int d = idx % DIN;
    int q = idx / DIN;
    int m0 = q << 2;
    int l0 = m0 & (LL - 1);
    float w0 = cw[d * 4], w1 = cw[d * 4 + 1], w2 = cw[d * 4 + 2], w3 = cw[d * 4 + 3];
    float bias = cb[d];
    float xw[7];
    #pragma unroll
    for (int i = 0; i < 7; i++) {
        int l = l0 + i - 3;
        xw[i] = (l >= 0) ? __half2float(g_xz[(size_t)(m0 + i - 3) * (2 * DIN) + d]) : 0.f;
    }
    #pragma unroll
    for (int t = 0; t < 4; t++) {
        float acc = bias;
        acc = fmaf(xw[t],     w0, acc);
        acc = fmaf(xw[t + 1], w1, acc);
        acc = fmaf(xw[t + 2], w2, acc);
        acc = fmaf(xw[t + 3], w3, acc);
        g_xc[(size_t)(m0 + t) * DIN + d] = __float2half_rn(silu_f(acc));
    }
}

// ----------------------------------------------------------------------------
// dbc = xc @ W_x^T  — tiled GEMM (BM=64 tokens, all 33 outputs, BK=64)
// ----------------------------------------------------------------------------
__global__ __launch_bounds__(256)
void dbc_kernel(const float* __restrict__ Wx) {
    __shared__ float sA[64][65];
    __shared__ float sB[33][65];
    int tid = threadIdx.x;
    int m0 = blockIdx.x * 64;
    int row = tid >> 2;
    int og  = tid & 3;
    float acc[9];
    #pragma unroll
    for (int j = 0; j < 9; j++) acc[j] = 0.f;

    for (int k0 = 0; k0 < DIN; k0 += 64) {
        #pragma unroll
        for (int i = tid; i < 64 * 16; i += 256) {
            int r = i >> 4;
            int c4 = (i & 15) << 2;
            uint2 raw = *(const uint2*)(g_xc + (size_t)(m0 + r) * DIN + k0 + c4);
            __half2 h01 = *(__half2*)&raw.x;
            __half2 h23 = *(__half2*)&raw.y;
            float2 f01 = __half22float2(h01);
            float2 f23 = __half22float2(h23);
            sA[r][c4] = f01.x; sA[r][c4 + 1] = f01.y; sA[r][c4 + 2] = f23.x; sA[r][c4 + 3] = f23.y;
        }
        for (int i = tid; i < 33 * 16; i += 256) {
            int r = i >> 4;
            int c4 = (i & 15) << 2;
            float4 v = *(const float4*)(Wx + (size_t)r * DIN + k0 + c4);
            sB[r][c4] = v.x; sB[r][c4 + 1] = v.y; sB[r][c4 + 2] = v.z; sB[r][c4 + 3] = v.w;
        }
        __syncthreads();
        #pragma unroll 8
        for (int kk = 0; kk < 64; kk++) {
            float a = sA[row][kk];
            #pragma unroll
            for (int j = 0; j < 9; j++) {
                int o = og + 4 * j;
                if (o < 33) acc[j] = fmaf(a, sB[o][kk], acc[j]);
            }
        }
        __syncthreads();
    }
    #pragma unroll
    for (int j = 0; j < 9; j++) {
        int o = og + 4 * j;
        if (o < 33) g_dbc[(size_t)(m0 + row) * 33 + o] = acc[j];
    }
}

// ----------------------------------------------------------------------------
// Chunked selective scan (CH=16, CLEN=128). Thread = one d-channel, 16 states.
// dbc/u staged through smem in 32-step chunks.
// ----------------------------------------------------------------------------
#define SC_DPB 128   // d-channels per block = blockDim

__global__ __launch_bounds__(SC_DPB)
void scan_phase1(const float* __restrict__ dt_w, const float* __restrict__ dt_b,
                 const float* __restrict__ A_log) {
    __shared__ float sdbc[32 * 33];
    __shared__ __half su[32][SC_DPB];

    int blk = blockIdx.x;
    const int DB = DIN / SC_DPB;          // 12
    int dblk = blk % DB;
    int tmp = blk / DB;
    int c = tmp % CH;
    int b = tmp / CH;
    int d0 = dblk * SC_DPB;
    int d = d0 + threadIdx.x;

    float A[NN], h[NN];
    #pragma unroll
    for (int j = 0; j < NN; j++) {
        A[j] = -expf(A_log[d * NN + j]);
        h[j] = 0.f;
    }
    float dtw = dt_w[d], dtb = dt_b[d];
    float sumdelta = 0.f;
    size_t mbase = (size_t)b * LL + (size_t)c * CLEN;

    for (int l0 = 0; l0 < CLEN; l0 += 32) {
        // stage dbc rows [l0, l0+32)
        for (int i = threadIdx.x; i < 32 * 33; i += SC_DPB)
            sdbc[i] = g_dbc[(mbase + l0) * 33 + i];
        // stage u
        #pragma unroll
        for (int i = 0; i < 32; i += SC_DPB / 4) { }
        for (int i = threadIdx.x; i < 32 * SC_DPB; i += SC_DPB) {
            int r = i / SC_DPB, cc = i % SC_DPB;
            su[r][cc] = g_xc[(mbase + l0 + r) * DIN + d0 + cc];
        }
        __syncthreads();
        #pragma unroll 4
        for (int li = 0; li < 32; li++) {
            const float* row = sdbc + li * 33;
            float dt = row[0];
            float sp_in = fmaf(dt, dtw, dtb);
            float delta = (sp_in > 20.f) ? sp_in : log1pf(__expf(sp_in));
            sumdelta += delta;
            float u = __half2float(su[li][threadIdx.x]);
            float du = delta * u;
            #pragma unroll
            for (int j = 0; j < NN; j++) {
                float dA = __expf(delta * A[j]);
                h[j] = fmaf(dA, h[j], du * row[1 + j]);
            }
        }
        __syncthreads();
    }
    size_t base = (((size_t)(b * CH + c)) * DIN + d) * NN;
    #pragma unroll
    for (int j = 0; j < NN; j += 4) {
        float4 st; st.x = h[j]; st.y = h[j + 1]; st.z = h[j + 2]; st.w = h[j + 3];
        *(float4*)(g_carry + base + j) = st;
    }
    g_sumd[(b * CH + c) * DIN + d] = sumdelta;
}

__global__ void scan_phase2(const float* __restrict__ A_log) {
    int idx = blockIdx.x * blockDim.x + threadIdx.x;
    if (idx >= BB * DIN * NN) return;
    int n = idx % NN;
    int d = (idx / NN) % DIN;
    int b = idx / (NN * DIN);
    float A = -expf(A_log[d * NN + n]);
    float h = 0.f;
    #pragma unroll
    for (int c = 0; c < CH; c++) {
        size_t o = (((size_t)(b * CH + c)) * DIN + d) * NN + n;
        float loc = g_carry[o];
        g_carry[o] = h;
        float P = __expf(A * g_sumd[(b * CH + c) * DIN + d]);
        h = fmaf(P, h, loc);
    }
}

__global__ __launch_bounds__(SC_DPB)
void scan_phase3(const float* __restrict__ dt_w, const float* __restrict__ dt_b,
                 const float* __restrict__ A_log, const float* __restrict__ D_param) {
    __shared__ float sdbc[32 * 33];
    __shared__ __half su[32][SC_DPB];
    __shared__ __half sz[32][SC_DPB];

    int blk = blockIdx.x;
    const int DB = DIN / SC_DPB;
    int dblk = blk % DB;
    int tmp = blk / DB;
    int c = tmp % CH;
    int b = tmp / CH;
    int d0 = dblk * SC_DPB;
    int d = d0 + threadIdx.x;

    float A[NN], h[NN];
    size_t cbase = (((size_t)(b * CH + c)) * DIN + d) * NN;
    #pragma unroll
    for (int j = 0; j < NN; j += 4) {
        float4 h4 = *(const float4*)(g_carry + cbase + j);
        h[j] = h4.x; h[j + 1] = h4.y; h[j + 2] = h4.z; h[j + 3] = h4.w;
    }
    #pragma unroll
    for (int j = 0; j < NN; j++)
        A[j] = -expf(A_log[d * NN + j]);

    float dtw = dt_w[d], dtb = dt_b[d], Dp = D_param[d];
    size_t mbase = (size_t)b * LL + (size_t)c * CLEN;

    for (int l0 = 0; l0 < CLEN; l0 += 32) {
        for (int i = threadIdx.x; i < 32 * 33; i += SC_DPB)
            sdbc[i] = g_dbc[(mbase + l0) * 33 + i];
        for (int i = threadIdx.x; i < 32 * SC_DPB; i += SC_DPB) {
            int r = i / SC_DPB, cc = i % SC_DPB;
            su[r][cc] = g_xc[(mbase + l0 + r) * DIN + d0 + cc];
            sz[r][cc] = g_xz[(mbase + l0 + r) * (2 * DIN) + DIN + d0 + cc];
        }
        __syncthreads();
        #pragma unroll 4
        for (int li = 0; li < 32; li++) {
            const float* row = sdbc + li * 33;
            float dt = row[0];
            float sp_in = fmaf(dt, dtw, dtb);
            float delta = (sp_in > 20.f) ? sp_in : log1pf(__expf(sp_in));
            float u = __half2float(su[li][threadIdx.x]);
            float du = delta * u;
            float y = 0.f;
            #pragma unroll
            for (int j = 0; j < NN; j++) {
                float dA = __expf(delta * A[j]);
                h[j] = fmaf(dA, h[j], du * row[1 + j]);
                y = fmaf(h[j], row[17 + j], y);
            }
            float yy = fmaf(u, Dp, y);
            float z = __half2float(sz[li][threadIdx.x]);
            g_y[(mbase + l0 + li) * DIN + d] = __float2half_rn(yy * silu_f(z));
        }
        __syncthreads();
    }
}

// ----------------------------------------------------------------------------
// Launch
// ----------------------------------------------------------------------------
extern "C" void kernel_launch(void* const* d_in, const int* in_sizes, int n_in,
                              void* d_out, int out_size) {
    const float* x         = (const float*)d_in[0];
    const float* norm_w    = (const float*)d_in[1];
    const float* in_norm_w = (const float*)d_in[2];
    const float* W_in      = (const float*)d_in[3];
    const float* conv_w    = (const float*)d_in[4];
    const float* conv_b    = (const float*)d_in[5];
    const float* W_x       = (const float*)d_in[6];
    const float* dt_w      = (const float*)d_in[7];
    const float* dt_b      = (const float*)d_in[8];
    const float* A_log     = (const float*)d_in[9];
    const float* D_param   = (const float*)d_in[10];
    const float* out_norm_w = (const float*)d_in[11];
    const float* W_out      = (const float*)d_in[12];
    float* out = (float*)d_out;

    float *p_part, *p_scale;
    __half *p_xz, *p_y, *p_A1, *p_A2, *p_B1, *p_B2;
    cudaGetSymbolAddress((void**)&p_xz,    g_xz);
    cudaGetSymbolAddress((void**)&p_y,     g_y);
    cudaGetSymbolAddress((void**)&p_part,  g_part);
    cudaGetSymbolAddress((void**)&p_scale, g_scale);
    cudaGetSymbolAddress((void**)&p_A1,    g_A1);
    cudaGetSymbolAddress((void**)&p_A2,    g_A2);
    cudaGetSymbolAddress((void**)&p_B1,    g_B1);
    cudaGetSymbolAddress((void**)&p_B2,    g_B2);

    cudaFuncSetAttribute(gemm_f16_kernel<true>,  cudaFuncAttributeMaxDynamicSharedMemorySize, GEMM_SMEM);
    cudaFuncSetAttribute(gemm_f16_kernel<false>, cudaFuncAttributeMaxDynamicSharedMemorySize, GEMM_SMEM);

    // 1) Weight scales (merged)
    abssum2_kernel<<<512, 256>>>(W_in, W_out, p_part);
    finalize2_kernel<<<2, 256>>>(p_part, p_scale);

    // 2) Ternary-quantize both weights to fp16 (merged)
    quant2_kernel<<<2048, 256>>>(W_in, W_out, p_B1, p_B2, p_scale);

    // 3) Fused double RMSNorm x -> fp16 A1
    rmsnorm2_f16_kernel<<<BL, 256>>>(x, norm_w, in_norm_w, p_A1);

    // 4) xz = (A1 @ B1^T) * scale0   [8192 x 3072] -> fp16
    {
        dim3 grid(2 * DIN / 128, BL / 128);
        gemm_f16_kernel<true><<<grid, 256, GEMM_SMEM>>>(p_A1, p_B1, p_xz, nullptr, p_scale, BL, 2 * DIN, DM);
    }

    // 5) Causal conv + SiLU (4 tokens/thread)
    conv_silu_kernel<<<((BL / 4) * DIN + 255) / 256, 256>>>(conv_w, conv_b);

    // 6) dbc = xc @ W_x^T (tiled)
    dbc_kernel<<<BL / 64, 256>>>(W_x);

    // 7) Chunked selective scan (CH=16, d-mapped threads)
    scan_phase1<<<BB * CH * (DIN / SC_DPB), SC_DPB>>>(dt_w, dt_b, A_log);
    scan_phase2<<<(BB * DIN * NN + 255) / 256, 256>>>(A_log);
    scan_phase3<<<BB * CH * (DIN / SC_DPB), SC_DPB>>>(dt_w, dt_b, A_log, D_param);

    // 8) RMSNorm y -> fp16 A2
    rmsnorm_h2h_kernel<6><<<BL, 256>>>(p_y, out_norm_w, p_A2);

    // 9) out = (A2 @ B2^T) * scale1 + residual(x)   [8192 x 768] fp32
    {
        dim3 grid(DM / 128, BL / 128);
        gemm_f16_kernel<false><<<grid, 256, GEMM_SMEM>>>(p_A2, p_B2, out, x, p_scale + 1, BL, DM, DIN);
    }
}

// round 9
// speedup vs baseline: 6.2219x; 1.0433x over previous
#include <cuda_runtime.h>
#include <cuda_fp16.h>
#include <math.h>
#include <stdint.h>

// Problem dims (fixed for this instance)
#define BB   4
#define LL   2048
#define DM   768
#define DIN  1536
#define NN   16
#define KK   4
#define BL   (BB*LL)          // 8192 tokens
#define CH   16               // scan chunks
#define CLEN (LL/CH)          // 128

#define NWIN  (2*DIN*DM)      // 2359296
#define NWOUT (DM*DIN)        // 1179648

// ----------------------------------------------------------------------------
// Device scratch
// ----------------------------------------------------------------------------
__device__ __half g_xz [BL*2*DIN];               // bitlinear output [x_path | z] (fp16)
__device__ __half g_xc [BL*DIN];                 // conv + silu (fp16)
__device__ float  g_dbc[BL*33];                  // [dt | B(16) | C(16)]
__device__ __half g_y  [BL*DIN];                 // scan output * silu(z) (fp16)
__device__ __half g_A1[BL*DM];                   // fp16 rmsnorm2(x) [M, DM]
__device__ __half g_A2[BL*DIN];                  // fp16 rmsnorm(y)  [M, DIN]
__device__ __half g_B1[NWIN];                    // ternary W_in  fp16 [3072, 768]
__device__ __half g_B2[NWOUT];                   // ternary W_out fp16 [768, 1536]
__device__ float g_carry[BB*CH*DIN*NN];          // chunk carries / h_in (in-place)
__device__ float g_sumd [BB*CH*DIN];             // per-chunk sum of delta
__device__ float g_part[512];                    // reduction partials
__device__ float g_scale[2];                     // scales for W_in / W_out

// ----------------------------------------------------------------------------
// Helpers
// ----------------------------------------------------------------------------
__device__ __forceinline__ float block_reduce_sum(float v, float* sred) {
    #pragma unroll
    for (int s = 16; s; s >>= 1) v += __shfl_xor_sync(0xffffffffu, v, s);
    int w = threadIdx.x >> 5;
    __syncthreads();
    if ((threadIdx.x & 31) == 0) sred[w] = v;
    __syncthreads();
    float t = 0.f;
    int nw = blockDim.x >> 5;
    for (int i = 0; i < nw; i++) t += sred[i];
    return t;
}

__device__ __forceinline__ float silu_f(float x) {
    return x / (1.f + __expf(-x));
}

__device__ __forceinline__ float softplus_f(float x) {
    return (x > 20.f) ? x : __logf(1.f + __expf(x));
}

__device__ __forceinline__ uint32_t cvta_s(const void* p) {
    return (uint32_t)__cvta_generic_to_shared(p);
}

__device__ __forceinline__ void cpa16(uint32_t s, const void* g) {
    asm volatile("cp.async.cg.shared.global [%0], [%1], 16;" :: "r"(s), "l"(g));
}
__device__ __forceinline__ void cpa_commit() {
    asm volatile("cp.async.commit_group;");
}
template <int N_>
__device__ __forceinline__ void cpa_wait() {
    asm volatile("cp.async.wait_group %0;" :: "n"(N_));
}

__device__ __forceinline__ void ldsm4(uint32_t& r0, uint32_t& r1, uint32_t& r2, uint32_t& r3,
                                      uint32_t addr) {
    asm volatile("ldmatrix.sync.aligned.m8n8.x4.shared.b16 {%0,%1,%2,%3}, [%4];"
                 : "=r"(r0), "=r"(r1), "=r"(r2), "=r"(r3) : "r"(addr));
}

__device__ __forceinline__ void mma16816(float* d, const uint32_t* a, const uint32_t* b) {
    asm volatile("mma.sync.aligned.m16n8k16.row.col.f32.f16.f16.f32 "
                 "{%0,%1,%2,%3},{%4,%5,%6,%7},{%8,%9},{%0,%1,%2,%3};"
                 : "+f"(d[0]), "+f"(d[1]), "+f"(d[2]), "+f"(d[3])
                 : "r"(a[0]), "r"(a[1]), "r"(a[2]), "r"(a[3]), "r"(b[0]), "r"(b[1]));
}

// dA[j] = E^(j+1), j=0..15, log-depth multiply tree
__device__ __forceinline__ void epowers16(float E, float* dA) {
    dA[0] = E;
    dA[1] = E * E;
    dA[2] = dA[1] * E;
    dA[3] = dA[1] * dA[1];
    dA[4] = dA[3] * E;
    dA[5] = dA[3] * dA[1];
    dA[6] = dA[3] * dA[2];
    dA[7] = dA[3] * dA[3];
    dA[8] = dA[7] * E;
    dA[9] = dA[7] * dA[1];
    dA[10] = dA[7] * dA[2];
    dA[11] = dA[7] * dA[3];
    dA[12] = dA[7] * dA[4];
    dA[13] = dA[7] * dA[5];
    dA[14] = dA[7] * dA[6];
    dA[15] = dA[7] * dA[7];
}

// ----------------------------------------------------------------------------
// Weight quantization (deterministic 2-phase mean|W|) — merged kernels
// ----------------------------------------------------------------------------
__global__ void abssum2_kernel(const float* __restrict__ W1, const float* __restrict__ W2,
                               float* __restrict__ part) {
    __shared__ float sred[8];
    const float* W = (blockIdx.x < 256) ? W1 : W2;
    int n = (blockIdx.x < 256) ? NWIN : NWOUT;
    int blk = blockIdx.x & 255;
    float s = 0.f;
    for (int i = blk * blockDim.x + threadIdx.x; i < n; i += 256 * blockDim.x)
        s += fabsf(W[i]);
    float tot = block_reduce_sum(s, sred);
    if (threadIdx.x == 0) part[blockIdx.x] = tot;
}

__global__ void finalize2_kernel(const float* __restrict__ part, float* __restrict__ scale) {
    __shared__ float sred[8];
    float inv_n = (blockIdx.x == 0) ? (1.f / (float)NWIN) : (1.f / (float)NWOUT);
    float tot = block_reduce_sum(part[blockIdx.x * 256 + threadIdx.x], sred);
    if (threadIdx.x == 0) scale[blockIdx.x] = fmaxf(tot * inv_n, 1e-5f);
}

// Ternary quantize both weights -> fp16 {-1,0,1}
__global__ void quant2_kernel(const float* __restrict__ W1, const float* __restrict__ W2,
                              __half* __restrict__ B1, __half* __restrict__ B2,
                              const float* __restrict__ sp) {
    float s0 = sp[0], s1 = sp[1];
    const int total = NWIN + NWOUT;
    for (int i = blockIdx.x * blockDim.x + threadIdx.x; i < total; i += gridDim.x * blockDim.x) {
        if (i < NWIN) {
            float wn = fminf(fmaxf(W1[i] / s0, -1.f), 1.f);
            B1[i] = __float2half_rn(rintf(wn));
        } else {
            int j = i - NWIN;
            float wn = fminf(fmaxf(W2[j] / s1, -1.f), 1.f);
            B2[j] = __float2half_rn(rintf(wn));
        }
    }
}

// ----------------------------------------------------------------------------
// Fused double RMSNorm (x -> rmsnorm(w1) -> rmsnorm(w2)) with fp16 out
// ----------------------------------------------------------------------------
__global__ void rmsnorm2_f16_kernel(const float* __restrict__ in,
                                    const float* __restrict__ w1,
                                    const float* __restrict__ w2,
                                    __half* __restrict__ out) {
    __shared__ float sred[8];
    const int D = 768;
    size_t base = (size_t)blockIdx.x * D;
    float v[3], t[3];
    float ss = 0.f;
    #pragma unroll
    for (int i = 0; i < 3; i++) {
        float x = in[base + threadIdx.x + (i << 8)];
        v[i] = x;
        ss = fmaf(x, x, ss);
    }
    float tot = block_reduce_sum(ss, sred);
    float r1 = rsqrtf(tot / (float)D + 1e-6f);
    float ss2 = 0.f;
    #pragma unroll
    for (int i = 0; i < 3; i++) {
        int c = threadIdx.x + (i << 8);
        t[i] = v[i] * r1 * w1[c];
        ss2 = fmaf(t[i], t[i], ss2);
    }
    float tot2 = block_reduce_sum(ss2, sred);
    float r2 = rsqrtf(tot2 / (float)D + 1e-6f);
    #pragma unroll
    for (int i = 0; i < 3; i++) {
        int c = threadIdx.x + (i << 8);
        out[base + c] = __float2half_rn(t[i] * r2 * w2[c]);
    }
}

// RMSNorm with fp16 input and fp16 output (for y, D = 1536)
template <int CNT>
__global__ void rmsnorm_h2h_kernel(const __half* __restrict__ in, const float* __restrict__ w,
                                   __half* __restrict__ out) {
    __shared__ float sred[8];
    const int D = CNT * 256;
    size_t base = (size_t)blockIdx.x * D;
    float v[CNT];
    float ss = 0.f;
    #pragma unroll
    for (int i = 0; i < CNT; i++) {
        float x = __half2float(in[base + threadIdx.x + (i << 8)]);
        v[i] = x;
        ss = fmaf(x, x, ss);
    }
    float tot = block_reduce_sum(ss, sred);
    float r = rsqrtf(tot / (float)D + 1e-6f);
    #pragma unroll
    for (int i = 0; i < CNT; i++) {
        int c = threadIdx.x + (i << 8);
        out[base + c] = __float2half_rn(v[i] * r * w[c]);
    }
}

// ----------------------------------------------------------------------------
// fp16 tensor-core GEMM: C[M,N] = (A[M,K] * B[N,K]^T) * scale (+Res)
// BM=128, BN=256, BK=64, 8 warps (2x4), 64x64 warp tiles, 3-stage cp.async.
// HALF_OUT: write __half C (no residual). else: float C (+Res).
// ----------------------------------------------------------------------------
#define LDS_   72
#define TILEA  (128 * LDS_)
#define TILEB  (256 * LDS_)
#define GSTG   3
#define GEMM_SMEM (GSTG * (TILEA + TILEB) * 2)   // 165888 bytes

template <bool HALF_OUT>
__global__ __launch_bounds__(256)
void gemm_f16_kernel(const __half* __restrict__ A,
                     const __half* __restrict__ B,
                     void* __restrict__ Cv, const float* __restrict__ Res,
                     const float* __restrict__ scalep,
                     int M, int N, int K2) {
    extern __shared__ __half smem_[];
    __half* sA = smem_;                       // GSTG stages of TILEA
    __half* sB = smem_ + GSTG * TILEA;        // GSTG stages of TILEB

    int tid  = threadIdx.x;
    int lane = tid & 31;
    int warp = tid >> 5;
    int wm = warp & 1;           // 0..1 (M, 64 rows each)
    int wn = warp >> 1;          // 0..3 (N, 64 cols each)
    int bm = blockIdx.y * 128;
    int bn = blockIdx.x * 256;

    // loader mapping: lr in 0..31, lc = 8-half columns
    int lr = tid >> 3;
    int lc = (tid & 7) << 3;
    const __half* AgBase = A + (size_t)bm * K2 + lc;
    const __half* BgBase = B + (size_t)bn * K2 + lc;

    uint32_t sAbase = cvta_s(sA);
    uint32_t sBbase = cvta_s(sB);

    int aRow = wm * 64 + (lane & 15);
    int aCol = (lane >> 4) << 3;
    uint32_t aFrag = (uint32_t)((aRow * LDS_ + aCol) * 2);   // + mt*16*LDS_*2
    int bRow = wn * 64 + (((lane >> 4) & 1) << 3) + (lane & 7);
    int bCol = ((lane >> 3) & 1) << 3;
    uint32_t bFrag = (uint32_t)((bRow * LDS_ + bCol) * 2);   // + p*16*LDS_*2

    float acc[4][8][4];
    #pragma unroll
    for (int i = 0; i < 4; i++)
        #pragma unroll
        for (int j = 0; j < 8; j++)
            #pragma unroll
            for (int k = 0; k < 4; k++) acc[i][j][k] = 0.f;

    int KT = K2 >> 6;

    auto load_stage = [&](int s, int kt) {
        uint32_t ao = sAbase + (uint32_t)(s * TILEA * 2);
        uint32_t bo = sBbase + (uint32_t)(s * TILEB * 2);
        size_t ko = (size_t)kt << 6;
        #pragma unroll
        for (int i = 0; i < 4; i++) {
            int r = lr + (i << 5);
            cpa16(ao + (uint32_t)((r * LDS_ + lc) * 2), AgBase + (size_t)r * K2 + ko);
        }
        #pragma unroll
        for (int i = 0; i < 8; i++) {
            int r = lr + (i << 5);
            cpa16(bo + (uint32_t)((r * LDS_ + lc) * 2), BgBase + (size_t)r * K2 + ko);
        }
    };

    load_stage(0, 0); cpa_commit();
    if (KT > 1) { load_stage(1, 1); cpa_commit(); }

    int s = 0;
    for (int kt = 0; kt < KT; kt++) {
        if (kt + 1 < KT) cpa_wait<1>(); else cpa_wait<0>();
        __syncthreads();
        if (kt + 2 < KT) {
            int sn = s + 2; if (sn >= GSTG) sn -= GSTG;
            load_stage(sn, kt + 2);
            cpa_commit();
        }

        uint32_t aS = sAbase + (uint32_t)(s * TILEA * 2) + aFrag;
        uint32_t bS = sBbase + (uint32_t)(s * TILEB * 2) + bFrag;
        #pragma unroll
        for (int ks = 0; ks < 4; ks++) {
            uint32_t kb = (uint32_t)(ks * 16 * 2);
            uint32_t a[4][4];
            #pragma unroll
            for (int mt = 0; mt < 4; mt++)
                ldsm4(a[mt][0], a[mt][1], a[mt][2], a[mt][3],
                      aS + (uint32_t)(mt * 16 * LDS_ * 2) + kb);
            uint32_t bf[8][2];
            #pragma unroll
            for (int p = 0; p < 4; p++)
                ldsm4(bf[2 * p][0], bf[2 * p][1], bf[2 * p + 1][0], bf[2 * p + 1][1],
                      bS + (uint32_t)(p * 16 * LDS_ * 2) + kb);
            #pragma unroll
            for (int mt = 0; mt < 4; mt++)
                #pragma unroll
                for (int nt = 0; nt < 8; nt++)
                    mma16816(acc[mt][nt], a[mt], bf[nt]);
        }
        s++; if (s >= GSTG) s = 0;
    }

    float sc = __ldg(scalep);
    int er = bm + wm * 64 + (lane >> 2);
    int ec = bn + wn * 64 + ((lane & 3) << 1);
    #pragma unroll
    for (int mt = 0; mt < 4; mt++) {
        #pragma unroll
        for (int h = 0; h < 2; h++) {
            int row = er + mt * 16 + h * 8;
            #pragma unroll
            for (int nt = 0; nt < 8; nt++) {
                size_t off = (size_t)row * N + ec + nt * 8;
                float ox = acc[mt][nt][2 * h + 0] * sc;
                float oy = acc[mt][nt][2 * h + 1] * sc;
                if (HALF_OUT) {
                    *(__half2*)((__half*)Cv + off) = __floats2half2_rn(ox, oy);
                } else {
                    float2 o;
                    o.x = ox + Res[off];
                    o.y = oy + Res[off + 1];
                    *(float2*)((float*)Cv + off) = o;
                }
            }
        }
    }
}

// ----------------------------------------------------------------------------
// Causal depthwise conv (K=4) + bias + SiLU — 4 tokens per thread (fp16 io)
// ----------------------------------------------------------------------------
__global__ void conv_silu_kernel(const float* __restrict__ cw, const float* __restrict__ cb) {
    int idx = blockIdx.x * blockDim.x + threadIdx.x;
    const int TOT = (BL / 4) * DIN;
    if (idx >= TOT) return;
    int d = idx % DIN;
    int q = idx / DIN;
    int m0 = q << 2;
    int l0 = m0 & (LL - 1);
    float w0 = cw[d * 4], w1 = cw[d * 4 + 1], w2 = cw[d * 4 + 2], w3 = cw[d * 4 + 3];
    float bias = cb[d];
    float xw[7];
    #pragma unroll
    for (int i = 0; i < 7; i++) {
        int l = l0 + i - 3;
        xw[i] = (l >= 0) ? __half2float(g_xz[(size_t)(m0 + i - 3) * (2 * DIN) + d]) : 0.f;
    }
    #pragma unroll
    for (int t = 0; t < 4; t++) {
        float acc = bias;
        acc = fmaf(xw[t],     w0, acc);
        acc = fmaf(xw[t + 1], w1, acc);
        acc = fmaf(xw[t + 2], w2, acc);
        acc = fmaf(xw[t + 3], w3, acc);
        g_xc[(size_t)(m0 + t) * DIN + d] = __float2half_rn(silu_f(acc));
    }
}

// ----------------------------------------------------------------------------
// dbc = xc @ W_x^T  — tiled GEMM (BM=64 tokens, all 33 outputs, BK=64)
// ----------------------------------------------------------------------------
__global__ __launch_bounds__(256)
void dbc_kernel(const float* __restrict__ Wx) {
    __shared__ float sA[64][65];
    __shared__ float sB[33][65];
    int tid = threadIdx.x;
    int m0 = blockIdx.x * 64;
    int row = tid >> 2;
    int og  = tid & 3;
    float acc[9];
    #pragma unroll
    for (int j = 0; j < 9; j++) acc[j] = 0.f;

    for (int k0 = 0; k0 < DIN; k0 += 64) {
        #pragma unroll
        for (int i = tid; i < 64 * 16; i += 256) {
            int r = i >> 4;
            int c4 = (i & 15) << 2;
            uint2 raw = *(const uint2*)(g_xc + (size_t)(m0 + r) * DIN + k0 + c4);
            __half2 h01 = *(__half2*)&raw.x;
            __half2 h23 = *(__half2*)&raw.y;
            float2 f01 = __half22float2(h01);
            float2 f23 = __half22float2(h23);
            sA[r][c4] = f01.x; sA[r][c4 + 1] = f01.y; sA[r][c4 + 2] = f23.x; sA[r][c4 + 3] = f23.y;
        }
        for (int i = tid; i < 33 * 16; i += 256) {
            int r = i >> 4;
            int c4 = (i & 15) << 2;
            float4 v = *(const float4*)(Wx + (size_t)r * DIN + k0 + c4);
            sB[r][c4] = v.x; sB[r][c4 + 1] = v.y; sB[r][c4 + 2] = v.z; sB[r][c4 + 3] = v.w;
        }
        __syncthreads();
        #pragma unroll 8
        for (int kk = 0; kk < 64; kk++) {
            float a = sA[row][kk];
            #pragma unroll
            for (int j = 0; j < 9; j++) {
                int o = og + 4 * j;
                if (o < 33) acc[j] = fmaf(a, sB[o][kk], acc[j]);
            }
        }
        __syncthreads();
    }
    #pragma unroll
    for (int j = 0; j < 9; j++) {
        int o = og + 4 * j;
        if (o < 33) g_dbc[(size_t)(m0 + row) * 33 + o] = acc[j];
    }
}

// ----------------------------------------------------------------------------
// Chunked selective scan (CH=16, CLEN=128). Thread = one d-channel, 16 states.
// dA_j computed as powers of E = exp(delta*A[0]) when A_j = (j+1)*A_0 (runtime
// checked; true for this problem's A_log = log(1..16)).
// ----------------------------------------------------------------------------
#define SC_DPB 128   // d-channels per block = blockDim

__global__ __launch_bounds__(SC_DPB)
void scan_phase1(const float* __restrict__ dt_w, const float* __restrict__ dt_b,
                 const float* __restrict__ A_log) {
    __shared__ float sdbc[32 * 33];
    __shared__ __half su[32][SC_DPB];

    int blk = blockIdx.x;
    const int DB = DIN / SC_DPB;          // 12
    int dblk = blk % DB;
    int tmp = blk / DB;
    int c = tmp % CH;
    int b = tmp / CH;
    int d0 = dblk * SC_DPB;
    int d = d0 + threadIdx.x;

    float A[NN], h[NN];
    #pragma unroll
    for (int j = 0; j < NN; j++) {
        A[j] = -expf(A_log[d * NN + j]);
        h[j] = 0.f;
    }
    bool fast = true;
    #pragma unroll
    for (int j = 1; j < NN; j++)
        fast = fast && (fabsf(A[j] - (float)(j + 1) * A[0]) <= 1e-5f * (float)(j + 1));

    float dtw = dt_w[d], dtb = dt_b[d];
    float sumdelta = 0.f;
    size_t mbase = (size_t)b * LL + (size_t)c * CLEN;

    for (int l0 = 0; l0 < CLEN; l0 += 32) {
        for (int i = threadIdx.x; i < 32 * 33; i += SC_DPB)
            sdbc[i] = g_dbc[(mbase + l0) * 33 + i];
        for (int i = threadIdx.x; i < 32 * SC_DPB; i += SC_DPB) {
            int r = i / SC_DPB, cc = i % SC_DPB;
            su[r][cc] = g_xc[(mbase + l0 + r) * DIN + d0 + cc];
        }
        __syncthreads();
        if (fast) {
            #pragma unroll 4
            for (int li = 0; li < 32; li++) {
                const float* row = sdbc + li * 33;
                float delta = softplus_f(fmaf(row[0], dtw, dtb));
                sumdelta += delta;
                float u = __half2float(su[li][threadIdx.x]);
                float du = delta * u;
                float dA[NN];
                epowers16(__expf(delta * A[0]), dA);
                #pragma unroll
                for (int j = 0; j < NN; j++)
                    h[j] = fmaf(dA[j], h[j], du * row[1 + j]);
            }
        } else {
            #pragma unroll 4
            for (int li = 0; li < 32; li++) {
                const float* row = sdbc + li * 33;
                float delta = softplus_f(fmaf(row[0], dtw, dtb));
                sumdelta += delta;
                float u = __half2float(su[li][threadIdx.x]);
                float du = delta * u;
                #pragma unroll
                for (int j = 0; j < NN; j++) {
                    float dA = __expf(delta * A[j]);
                    h[j] = fmaf(dA, h[j], du * row[1 + j]);
                }
            }
        }
        __syncthreads();
    }
    size_t base = (((size_t)(b * CH + c)) * DIN + d) * NN;
    #pragma unroll
    for (int j = 0; j < NN; j += 4) {
        float4 st; st.x = h[j]; st.y = h[j + 1]; st.z = h[j + 2]; st.w = h[j + 3];
        *(float4*)(g_carry + base + j) = st;
    }
    g_sumd[(b * CH + c) * DIN + d] = sumdelta;
}

__global__ void scan_phase2(const float* __restrict__ A_log) {
    int idx = blockIdx.x * blockDim.x + threadIdx.x;
    if (idx >= BB * DIN * NN) return;
    int n = idx % NN;
    int d = (idx / NN) % DIN;
    int b = idx / (NN * DIN);
    float A = -expf(A_log[d * NN + n]);
    float h = 0.f;
    #pragma unroll
    for (int c = 0; c < CH; c++) {
        size_t o = (((size_t)(b * CH + c)) * DIN + d) * NN + n;
        float loc = g_carry[o];
        g_carry[o] = h;
        float P = __expf(A * g_sumd[(b * CH + c) * DIN + d]);
        h = fmaf(P, h, loc);
    }
}

__global__ __launch_bounds__(SC_DPB)
void scan_phase3(const float* __restrict__ dt_w, const float* __restrict__ dt_b,
                 const float* __restrict__ A_log, const float* __restrict__ D_param) {
    __shared__ float sdbc[32 * 33];
    __shared__ __half su[32][SC_DPB];
    __shared__ __half sz[32][SC_DPB];

    int blk = blockIdx.x;
    const int DB = DIN / SC_DPB;
    int dblk = blk % DB;
    int tmp = blk / DB;
    int c = tmp % CH;
    int b = tmp / CH;
    int d0 = dblk * SC_DPB;
    int d = d0 + threadIdx.x;

    float A[NN], h[NN];
    size_t cbase = (((size_t)(b * CH + c)) * DIN + d) * NN;
    #pragma unroll
    for (int j = 0; j < NN; j += 4) {
        float4 h4 = *(const float4*)(g_carry + cbase + j);
        h[j] = h4.x; h[j + 1] = h4.y; h[j + 2] = h4.z; h[j + 3] = h4.w;
    }
    #pragma unroll
    for (int j = 0; j < NN; j++)
        A[j] = -expf(A_log[d * NN + j]);
    bool fast = true;
    #pragma unroll
    for (int j = 1; j < NN; j++)
        fast = fast && (fabsf(A[j] - (float)(j + 1) * A[0]) <= 1e-5f * (float)(j + 1));

    float dtw = dt_w[d], dtb = dt_b[d], Dp = D_param[d];
    size_t mbase = (size_t)b * LL + (size_t)c * CLEN;

    for (int l0 = 0; l0 < CLEN; l0 += 32) {
        for (int i = threadIdx.x; i < 32 * 33; i += SC_DPB)
            sdbc[i] = g_dbc[(mbase + l0) * 33 + i];
        for (int i = threadIdx.x; i < 32 * SC_DPB; i += SC_DPB) {
            int r = i / SC_DPB, cc = i % SC_DPB;
            su[r][cc] = g_xc[(mbase + l0 + r) * DIN + d0 + cc];
            sz[r][cc] = g_xz[(mbase + l0 + r) * (2 * DIN) + DIN + d0 + cc];
        }
        __syncthreads();
        if (fast) {
            #pragma unroll 4
            for (int li = 0; li < 32; li++) {
                const float* row = sdbc + li * 33;
                float delta = softplus_f(fmaf(row[0], dtw, dtb));
                float u = __half2float(su[li][threadIdx.x]);
                float du = delta * u;
                float dA[NN];
                epowers16(__expf(delta * A[0]), dA);
                float y = 0.f;
                #pragma unroll
                for (int j = 0; j < NN; j++) {
                    h[j] = fmaf(dA[j], h[j], du * row[1 + j]);
                    y = fmaf(h[j], row[17 + j], y);
                }
                float yy = fmaf(u, Dp, y);
                float z = __half2float(sz[li][threadIdx.x]);
                g_y[(mbase + l0 + li) * DIN + d] = __float2half_rn(yy * silu_f(z));
            }
        } else {
            #pragma unroll 4
            for (int li = 0; li < 32; li++) {
                const float* row = sdbc + li * 33;
                float delta = softplus_f(fmaf(row[0], dtw, dtb));
                float u = __half2float(su[li][threadIdx.x]);
                float du = delta * u;
                float y = 0.f;
                #pragma unroll
                for (int j = 0; j < NN; j++) {
                    float dA = __expf(delta * A[j]);
                    h[j] = fmaf(dA, h[j], du * row[1 + j]);
                    y = fmaf(h[j], row[17 + j], y);
                }
                float yy = fmaf(u, Dp, y);
                float z = __half2float(sz[li][threadIdx.x]);
                g_y[(mbase + l0 + li) * DIN + d] = __float2half_rn(yy * silu_f(z));
            }
        }
        __syncthreads();
    }
}

// ----------------------------------------------------------------------------
// Launch
// ----------------------------------------------------------------------------
extern "C" void kernel_launch(void* const* d_in, const int* in_sizes, int n_in,
                              void* d_out, int out_size) {
    const float* x         = (const float*)d_in[0];
    const float* norm_w    = (const float*)d_in[1];
    const float* in_norm_w = (const float*)d_in[2];
    const float* W_in      = (const float*)d_in[3];
    const float* conv_w    = (const float*)d_in[4];
    const float* conv_b    = (const float*)d_in[5];
    const float* W_x       = (const float*)d_in[6];
    const float* dt_w      = (const float*)d_in[7];
    const float* dt_b      = (const float*)d_in[8];
    const float* A_log     = (const float*)d_in[9];
    const float* D_param   = (const float*)d_in[10];
    const float* out_norm_w = (const float*)d_in[11];
    const float* W_out      = (const float*)d_in[12];
    float* out = (float*)d_out;

    float *p_part, *p_scale;
    __half *p_xz, *p_y, *p_A1, *p_A2, *p_B1, *p_B2;
    cudaGetSymbolAddress((void**)&p_xz,    g_xz);
    cudaGetSymbolAddress((void**)&p_y,     g_y);
    cudaGetSymbolAddress((void**)&p_part,  g_part);
    cudaGetSymbolAddress((void**)&p_scale, g_scale);
    cudaGetSymbolAddress((void**)&p_A1,    g_A1);
    cudaGetSymbolAddress((void**)&p_A2,    g_A2);
    cudaGetSymbolAddress((void**)&p_B1,    g_B1);
    cudaGetSymbolAddress((void**)&p_B2,    g_B2);

    cudaFuncSetAttribute(gemm_f16_kernel<true>,  cudaFuncAttributeMaxDynamicSharedMemorySize, GEMM_SMEM);
    cudaFuncSetAttribute(gemm_f16_kernel<false>, cudaFuncAttributeMaxDynamicSharedMemorySize, GEMM_SMEM);

    // 1) Weight scales (merged)
    abssum2_kernel<<<512, 256>>>(W_in, W_out, p_part);
    finalize2_kernel<<<2, 256>>>(p_part, p_scale);

    // 2) Ternary-quantize both weights to fp16 (merged)
    quant2_kernel<<<2048, 256>>>(W_in, W_out, p_B1, p_B2, p_scale);

    // 3) Fused double RMSNorm x -> fp16 A1
    rmsnorm2_f16_kernel<<<BL, 256>>>(x, norm_w, in_norm_w, p_A1);

    // 4) xz = (A1 @ B1^T) * scale0   [8192 x 3072] -> fp16
    {
        dim3 grid(2 * DIN / 256, BL / 128);
        gemm_f16_kernel<true><<<grid, 256, GEMM_SMEM>>>(p_A1, p_B1, p_xz, nullptr, p_scale, BL, 2 * DIN, DM);
    }

    // 5) Causal conv + SiLU (4 tokens/thread)
    conv_silu_kernel<<<((BL / 4) * DIN + 255) / 256, 256>>>(conv_w, conv_b);

    // 6) dbc = xc @ W_x^T (tiled)
    dbc_kernel<<<BL / 64, 256>>>(W_x);

    // 7) Chunked selective scan (CH=16, d-mapped threads)
    scan_phase1<<<BB * CH * (DIN / SC_DPB), SC_DPB>>>(dt_w, dt_b, A_log);
    scan_phase2<<<(BB * DIN * NN + 255) / 256, 256>>>(A_log);
    scan_phase3<<<BB * CH * (DIN / SC_DPB), SC_DPB>>>(dt_w, dt_b, A_log, D_param);

    // 8) RMSNorm y -> fp16 A2
    rmsnorm_h2h_kernel<6><<<BL, 256>>>(p_y, out_norm_w, p_A2);

    // 9) out = (A2 @ B2^T) * scale1 + residual(x)   [8192 x 768] fp32
    {
        dim3 grid(DM / 256, BL / 128);
        gemm_f16_kernel<false><<<grid, 256, GEMM_SMEM>>>(p_A2, p_B2, out, x, p_scale + 1, BL, DM, DIN);
    }
}